// round 9
// baseline (speedup 1.0000x reference)
#include <cuda_runtime.h>
#include <cuda_fp16.h>
#include <math.h>
#include <stdint.h>

// Problem constants
#define BB 2
#define SS 2048
#define EE 512
#define HH 8
#define DD 64
#define MM (BB * SS)   // 4096 rows

// Scratch (device globals; no allocation allowed)
__device__ float g_proj[MM * EE];

// fp16 operand arrays
__device__ __align__(16) __half g_Ax_hi[MM * EE];       // x split (qkv gemm A)
__device__ __align__(16) __half g_Ax_lo[MM * EE];
__device__ __align__(16) __half g_Qh[16 * 2048 * 64];   // [bh][s][d]
__device__ __align__(16) __half g_Ql[16 * 2048 * 64];
__device__ __align__(16) __half g_Kh[16 * 2048 * 64];
__device__ __align__(16) __half g_Kl[16 * 2048 * 64];
__device__ __align__(16) __half g_Vh[16 * 2048 * 64];   // single fp16
__device__ __align__(16) __half g_Av[MM * EE];          // attention out, single fp16
__device__ __align__(16) __half g_Bqkv_hi[3 * EE * EE]; // [n=z*512+h*64+d][e]
__device__ __align__(16) __half g_Bqkv_lo[3 * EE * EE];
__device__ __align__(16) __half g_Bp_hi[EE * EE];       // [n][k] = Wp[n][k]

// ---------------------------------------------------------------------------
// helpers
// ---------------------------------------------------------------------------
__device__ __forceinline__ uint32_t smem_u32(const void* p) {
    uint32_t a;
    asm("{ .reg .u64 t; cvta.to.shared.u64 t, %1; cvt.u32.u64 %0, t; }"
        : "=r"(a) : "l"(p));
    return a;
}
__device__ __forceinline__ uint32_t sw128(uint32_t off) {
    return off ^ ((off >> 3) & 0x70);
}
__device__ __forceinline__ void cpasync16(uint32_t dst, const void* src) {
    asm volatile("cp.async.cg.shared.global [%0], [%1], 16;"
                 :: "r"(dst), "l"(src) : "memory");
}
template <int N>
__device__ __forceinline__ void waitg() {
    asm volatile("cp.async.wait_group %0;" :: "n"(N) : "memory");
}
__device__ __forceinline__ void commitg() {
    asm volatile("cp.async.commit_group;" ::: "memory");
}
__device__ __forceinline__ void ldsm4(uint32_t& r0, uint32_t& r1, uint32_t& r2,
                                      uint32_t& r3, uint32_t a) {
    asm volatile("ldmatrix.sync.aligned.m8n8.x4.shared.b16 {%0,%1,%2,%3}, [%4];"
                 : "=r"(r0), "=r"(r1), "=r"(r2), "=r"(r3) : "r"(a));
}
__device__ __forceinline__ void ldsm4t(uint32_t& r0, uint32_t& r1, uint32_t& r2,
                                       uint32_t& r3, uint32_t a) {
    asm volatile("ldmatrix.sync.aligned.m8n8.x4.trans.shared.b16 {%0,%1,%2,%3}, [%4];"
                 : "=r"(r0), "=r"(r1), "=r"(r2), "=r"(r3) : "r"(a));
}
__device__ __forceinline__ void mma16816(float* c, const uint32_t* a,
                                         uint32_t b0, uint32_t b1) {
    asm volatile(
        "mma.sync.aligned.m16n8k16.row.col.f32.f16.f16.f32 "
        "{%0,%1,%2,%3}, {%4,%5,%6,%7}, {%8,%9}, {%0,%1,%2,%3};"
        : "+f"(c[0]), "+f"(c[1]), "+f"(c[2]), "+f"(c[3])
        : "r"(a[0]), "r"(a[1]), "r"(a[2]), "r"(a[3]), "r"(b0), "r"(b1));
}
__device__ __forceinline__ uint32_t packh2(float a, float b) {
    __half ha = __float2half_rn(a), hb = __float2half_rn(b);
    return (uint32_t)__half_as_ushort(ha) |
           ((uint32_t)__half_as_ushort(hb) << 16);
}
__device__ __forceinline__ void split2h(float a, float b, uint32_t& hi, uint32_t& lo) {
    __half ha = __float2half_rn(a), hb = __float2half_rn(b);
    float ra = a - __half2float(ha), rb = b - __half2float(hb);
    hi = (uint32_t)__half_as_ushort(ha) |
         ((uint32_t)__half_as_ushort(hb) << 16);
    __half la = __float2half_rn(ra), lb = __float2half_rn(rb);
    lo = (uint32_t)__half_as_ushort(la) |
         ((uint32_t)__half_as_ushort(lb) << 16);
}

// ---------------------------------------------------------------------------
// Merged prep: wqkv hi/lo, wp hi, x hi/lo in ONE launch.
// ---------------------------------------------------------------------------
#define N_WQKV (3 * EE * EE)            // 786432
#define N_WP   (EE * EE)                // 262144
#define N_X    (MM * EE)                // 2097152
__global__ void prep_all_kernel(const float* __restrict__ Wq,
                                const float* __restrict__ Wk,
                                const float* __restrict__ Wv,
                                const float* __restrict__ Wp,
                                const float* __restrict__ x) {
    int idx = blockIdx.x * 256 + threadIdx.x;
    if (idx < N_WQKV) {
        int n = idx >> 9, e = idx & 511;
        int z = n >> 9, h = (n >> 6) & 7, d = n & 63;
        const float* W = (z == 0) ? Wq : ((z == 1) ? Wk : Wv);
        float v = W[((size_t)h * EE + e) * DD + d];
        __half hi = __float2half_rn(v);
        g_Bqkv_hi[idx] = hi;
        g_Bqkv_lo[idx] = __float2half_rn(v - __half2float(hi));
    } else if (idx < N_WQKV + N_WP) {
        int i = idx - N_WQKV;
        g_Bp_hi[i] = __float2half_rn(Wp[i]);
    } else {
        int i = idx - N_WQKV - N_WP;
        float v = x[i];
        __half hi = __float2half_rn(v);
        g_Ax_hi[i] = hi;
        g_Ax_lo[i] = __float2half_rn(v - __half2float(hi));
    }
}
#define PREP_BLOCKS ((N_WQKV + N_WP + N_X) / 256)

// ---------------------------------------------------------------------------
// mma.sync GEMM: C[128 x 128] tile of A[M x 512] * B[N x 512]^T
// mode 0: qkv (N=1536). Q/K tiles (y<8): 3-pass -> hi/lo fp16 out.
//         V tiles (y>=8): 2-pass (AhBh + AlBh) -> single fp16 out.
// mode 1: proj (N=512), A = g_Av single fp16, 1-pass -> g_proj = acc+bp+x.
// 256 threads = 8 warps (4m x 2n). 3-stage cp.async pipeline (k=64).
// ---------------------------------------------------------------------------
#define STAGE_BYTES 65536
#define GEMM_SMEM (3 * STAGE_BYTES)   // 196608

__global__ __launch_bounds__(256, 1)
void gemm_mma_kernel(int mode, const float* __restrict__ x,
                     const float* __restrict__ bp) {
    extern __shared__ char sm[];
    const uint32_t smb = smem_u32(sm);
    const int t = threadIdx.x;
    const int w = t >> 5, l = t & 31;
    const int wm = w & 3, wn = w >> 2;
    const int gid = l >> 2, tig = l & 3;
    const int m0 = blockIdx.x * 128;
    const int n0 = blockIdx.y * 128;

    const bool useAl = (mode == 0);                    // pass Al·Bh
    const bool useBl = (mode == 0) && (blockIdx.y < 8); // pass Ah·Bl (Q/K only)

    const __half* Ah_g = (mode == 0) ? g_Ax_hi : g_Av;
    const __half* Al_g = g_Ax_lo;
    const __half* Bh_g = (mode == 0) ? g_Bqkv_hi : g_Bp_hi;
    const __half* Bl_g = g_Bqkv_lo;

    float acc[2][8][4];
#pragma unroll
    for (int i = 0; i < 2; i++)
#pragma unroll
        for (int j = 0; j < 8; j++)
#pragma unroll
            for (int c = 0; c < 4; c++) acc[i][j][c] = 0.f;

    auto issue_stage = [&](int s) {
        const int k0 = s * 64;
        const uint32_t sb = smb + (s % 3) * STAGE_BYTES;
        const __half* gsrc[4] = {Ah_g, Al_g, Bh_g, Bl_g};
#pragma unroll
        for (int tl = 0; tl < 4; tl++) {
            if (tl == 1 && !useAl) continue;
            if (tl == 3 && !useBl) continue;
            const uint32_t tbase = sb + tl * 16384;
            const __half* g = gsrc[tl];
            const int rbase = (tl < 2) ? m0 : n0;
#pragma unroll
            for (int i = 0; i < 4; i++) {
                int c = t + 256 * i;
                int row = c >> 3, cb = c & 7;
                uint32_t dst = tbase + sw128((uint32_t)(row * 128 + cb * 16));
                const __half* src =
                    g + (size_t)(rbase + row) * EE + k0 + cb * 8;
                cpasync16(dst, src);
            }
        }
        commitg();
    };

    issue_stage(0);
    issue_stage(1);

    const int li = l >> 3;
    const int lr = l & 7;

    for (int s = 0; s < 8; s++) {
        if (s < 7) waitg<1>(); else waitg<0>();
        __syncthreads();
        if (s + 2 < 8) issue_stage(s + 2);

        const uint32_t sb = smb + (s % 3) * STAGE_BYTES;

#pragma unroll
        for (int kk = 0; kk < 4; kk++) {
            uint32_t ah[2][4], al[2][4];
#pragma unroll
            for (int mt = 0; mt < 2; mt++) {
                int row = wm * 32 + mt * 16 + (li & 1) * 8 + lr;
                int cb = kk * 2 + (li >> 1);
                uint32_t off = sw128((uint32_t)(row * 128 + cb * 16));
                ldsm4(ah[mt][0], ah[mt][1], ah[mt][2], ah[mt][3], sb + off);
                if (useAl)
                    ldsm4(al[mt][0], al[mt][1], al[mt][2], al[mt][3],
                          sb + 16384 + off);
            }
#pragma unroll
            for (int h2 = 0; h2 < 2; h2++) {
                uint32_t bh[2][4], bl[2][4];
#pragma unroll
                for (int p2 = 0; p2 < 2; p2++) {
                    int ntb = h2 * 2 + p2;
                    int nrow = wn * 64 + ntb * 16 + (li >> 1) * 8 + lr;
                    int cb = kk * 2 + (li & 1);
                    uint32_t off = sw128((uint32_t)(nrow * 128 + cb * 16));
                    ldsm4(bh[p2][0], bh[p2][1], bh[p2][2], bh[p2][3],
                          sb + 32768 + off);
                    if (useBl)
                        ldsm4(bl[p2][0], bl[p2][1], bl[p2][2], bl[p2][3],
                              sb + 49152 + off);
                }
#pragma unroll
                for (int mt = 0; mt < 2; mt++)
#pragma unroll
                    for (int q = 0; q < 4; q++) {
                        int nt = h2 * 4 + q;
                        int p2 = q >> 1, od = q & 1;
                        float* c = acc[mt][nt];
                        mma16816(c, ah[mt], bh[p2][2 * od], bh[p2][2 * od + 1]);
                        if (useBl)
                            mma16816(c, ah[mt], bl[p2][2 * od], bl[p2][2 * od + 1]);
                        if (useAl)
                            mma16816(c, al[mt], bh[p2][2 * od], bh[p2][2 * od + 1]);
                    }
            }
        }
    }

    // ---- epilogue ----
    const int row0 = m0 + wm * 32 + gid;
    if (mode == 0) {
#pragma unroll
        for (int mt = 0; mt < 2; mt++) {
            int rg = row0 + mt * 16;
            int b = rg >> 11, sI = rg & 2047;
#pragma unroll
            for (int nt = 0; nt < 8; nt++) {
                int ng = n0 + wn * 64 + nt * 8 + 2 * tig;
                int z = ng >> 9, r9 = ng & 511;
                int h = r9 >> 6, d = r9 & 63;
                size_t base = (((size_t)(b * HH + h)) * SS + sI) * DD + d;
                if (z == 2) {
                    *(uint32_t*)(g_Vh + base) =
                        packh2(acc[mt][nt][0], acc[mt][nt][1]);
                    *(uint32_t*)(g_Vh + base + 8 * DD) =
                        packh2(acc[mt][nt][2], acc[mt][nt][3]);
                } else {
                    __half* oh = (z == 0) ? g_Qh : g_Kh;
                    __half* ol = (z == 0) ? g_Ql : g_Kl;
                    uint32_t hi, lo;
                    split2h(acc[mt][nt][0], acc[mt][nt][1], hi, lo);
                    *(uint32_t*)(oh + base) = hi;
                    *(uint32_t*)(ol + base) = lo;
                    split2h(acc[mt][nt][2], acc[mt][nt][3], hi, lo);
                    *(uint32_t*)(oh + base + 8 * DD) = hi;
                    *(uint32_t*)(ol + base + 8 * DD) = lo;
                }
            }
        }
    } else {
#pragma unroll
        for (int mt = 0; mt < 2; mt++) {
            int rg = row0 + mt * 16;
#pragma unroll
            for (int nt = 0; nt < 8; nt++) {
                int ng = n0 + wn * 64 + nt * 8 + 2 * tig;
                float2 bpv = *(const float2*)(bp + ng);
                float2 x0 = *(const float2*)(x + (size_t)rg * EE + ng);
                float2 x1 = *(const float2*)(x + (size_t)(rg + 8) * EE + ng);
                *(float2*)(g_proj + (size_t)rg * EE + ng) =
                    make_float2(acc[mt][nt][0] + bpv.x + x0.x,
                                acc[mt][nt][1] + bpv.y + x0.y);
                *(float2*)(g_proj + (size_t)(rg + 8) * EE + ng) =
                    make_float2(acc[mt][nt][2] + bpv.x + x1.x,
                                acc[mt][nt][3] + bpv.y + x1.y);
            }
        }
    }
}

// ---------------------------------------------------------------------------
// Flash attention: fp16 mma. QK^T 3-pass (Q,K hi/lo); PV 2-pass (P hi/lo,
// V single fp16). q-tile 128 rows, k-tiles of 64, 8 warps, 3-stage pipeline.
// Warp-level skip of fully-masked k-tiles.
// ---------------------------------------------------------------------------
#define NEG_BIG (-1e30f)
#define SM_QH 0
#define SM_QL 16384
#define SM_STG 32768
#define STG_SZ 24576          // Kh 8K + Kl 8K + V 8K
#define OFF_KH 0
#define OFF_KL 8192
#define OFF_V 16384
#define ATTN_SMEM (SM_STG + 3 * STG_SZ)   // 106496

__global__ __launch_bounds__(256, 1)
void attn_mma_kernel() {
    extern __shared__ char sm[];
    const uint32_t smb = smem_u32(sm);
    const int t = threadIdx.x;
    const int w = t >> 5, l = t & 31;
    const int gid = l >> 2, tig = l & 3;
    const int li = l >> 3, lr = l & 7;

    const int bid = blockIdx.x;
    const int bh = bid & 15;
    const int qt = 15 - (bid >> 4);       // heavy tiles first
    const int b = bh >> 3, h = bh & 7;
    const int qs = qt * 128;
    const size_t bhoff = (size_t)bh * SS * DD;
    const int ktmax = 2 * qt + 1;

    // ---- issue Q (128x64 hi+lo); joins commit group of stage 0 ----
#pragma unroll
    for (int arr = 0; arr < 2; arr++) {
        const __half* g = arr ? g_Ql : g_Qh;
        uint32_t base = smb + (arr ? SM_QL : SM_QH);
#pragma unroll
        for (int i = 0; i < 4; i++) {
            int c = t + 256 * i;
            int row = c >> 3, cb = c & 7;
            cpasync16(base + sw128((uint32_t)(row * 128 + cb * 16)),
                      g + bhoff + (size_t)(qs + row) * DD + cb * 8);
        }
    }

    auto issue_stage = [&](int kt) {
        const uint32_t sb = smb + SM_STG + (kt % 3) * STG_SZ;
        const __half* gs[3] = {g_Kh, g_Kl, g_Vh};
        const int ks = kt * 64;
#pragma unroll
        for (int arr = 0; arr < 3; arr++) {
#pragma unroll
            for (int i = 0; i < 2; i++) {
                int c = t + 256 * i;
                int row = c >> 3, cb = c & 7;
                cpasync16(sb + arr * 8192 + sw128((uint32_t)(row * 128 + cb * 16)),
                          gs[arr] + bhoff + (size_t)(ks + row) * DD + cb * 8);
            }
        }
        commitg();
    };

    issue_stage(0);
    issue_stage(1);

    float O[8][4];
#pragma unroll
    for (int i = 0; i < 8; i++)
#pragma unroll
        for (int j = 0; j < 4; j++) O[i][j] = 0.f;
    float m0 = NEG_BIG, m1 = NEG_BIG, l0 = 0.f, l1 = 0.f;

    const int rowstrip = qs + w * 16;
    const int qg0 = rowstrip + gid;
    const int qg1 = qg0 + 8;

    for (int kt = 0; kt <= ktmax; kt++) {
        if (kt < ktmax) waitg<1>(); else waitg<0>();
        __syncthreads();
        if (kt + 2 <= ktmax) issue_stage(kt + 2);

        const uint32_t sb = smb + SM_STG + (kt % 3) * STG_SZ;
        const int ks = kt * 64;

        // warp-uniform skip: this warp's 16-row strip fully masked
        if (ks > rowstrip + 15) continue;

        // ---- S = Q K^T (3-pass fp16 hi/lo) ----
        float S[8][4];
#pragma unroll
        for (int i = 0; i < 8; i++)
#pragma unroll
            for (int j = 0; j < 4; j++) S[i][j] = 0.f;

#pragma unroll
        for (int kk = 0; kk < 4; kk++) {
            uint32_t qh[4], ql[4];
            {
                int row = w * 16 + (li & 1) * 8 + lr;
                int cb = kk * 2 + (li >> 1);
                uint32_t off = sw128((uint32_t)(row * 128 + cb * 16));
                ldsm4(qh[0], qh[1], qh[2], qh[3], smb + SM_QH + off);
                ldsm4(ql[0], ql[1], ql[2], ql[3], smb + SM_QL + off);
            }
#pragma unroll
            for (int nb = 0; nb < 4; nb++) {
                uint32_t kh[4], kl[4];
                int nrow = nb * 16 + (li >> 1) * 8 + lr;
                int cb = kk * 2 + (li & 1);
                uint32_t off = sw128((uint32_t)(nrow * 128 + cb * 16));
                ldsm4(kh[0], kh[1], kh[2], kh[3], sb + OFF_KH + off);
                ldsm4(kl[0], kl[1], kl[2], kl[3], sb + OFF_KL + off);
#pragma unroll
                for (int od = 0; od < 2; od++) {
                    float* c = S[nb * 2 + od];
                    mma16816(c, qh, kh[2 * od], kh[2 * od + 1]);
                    mma16816(c, qh, kl[2 * od], kl[2 * od + 1]);
                    mma16816(c, ql, kh[2 * od], kh[2 * od + 1]);
                }
            }
        }

        // ---- causal mask ----
        if (ks + 63 > rowstrip) {
#pragma unroll
            for (int nt = 0; nt < 8; nt++) {
                int c0 = ks + nt * 8 + 2 * tig;
                if (c0 > qg0) S[nt][0] = NEG_BIG;
                if (c0 + 1 > qg0) S[nt][1] = NEG_BIG;
                if (c0 > qg1) S[nt][2] = NEG_BIG;
                if (c0 + 1 > qg1) S[nt][3] = NEG_BIG;
            }
        }

        // ---- online softmax ----
        float mx0 = NEG_BIG, mx1 = NEG_BIG;
#pragma unroll
        for (int nt = 0; nt < 8; nt++) {
            mx0 = fmaxf(mx0, fmaxf(S[nt][0], S[nt][1]));
            mx1 = fmaxf(mx1, fmaxf(S[nt][2], S[nt][3]));
        }
        mx0 = fmaxf(mx0, __shfl_xor_sync(0xffffffffu, mx0, 1));
        mx0 = fmaxf(mx0, __shfl_xor_sync(0xffffffffu, mx0, 2));
        mx1 = fmaxf(mx1, __shfl_xor_sync(0xffffffffu, mx1, 1));
        mx1 = fmaxf(mx1, __shfl_xor_sync(0xffffffffu, mx1, 2));

        float mn0 = fmaxf(m0, mx0), mn1 = fmaxf(m1, mx1);
        float sc0 = __expf(m0 - mn0), sc1 = __expf(m1 - mn1);
        float rs0 = 0.f, rs1 = 0.f;
#pragma unroll
        for (int nt = 0; nt < 8; nt++) {
            S[nt][0] = __expf(S[nt][0] - mn0);
            S[nt][1] = __expf(S[nt][1] - mn0);
            S[nt][2] = __expf(S[nt][2] - mn1);
            S[nt][3] = __expf(S[nt][3] - mn1);
            rs0 += S[nt][0] + S[nt][1];
            rs1 += S[nt][2] + S[nt][3];
        }
        rs0 += __shfl_xor_sync(0xffffffffu, rs0, 1);
        rs0 += __shfl_xor_sync(0xffffffffu, rs0, 2);
        rs1 += __shfl_xor_sync(0xffffffffu, rs1, 1);
        rs1 += __shfl_xor_sync(0xffffffffu, rs1, 2);
        l0 = l0 * sc0 + rs0;
        l1 = l1 * sc1 + rs1;
        m0 = mn0; m1 = mn1;
#pragma unroll
        for (int dt = 0; dt < 8; dt++) {
            O[dt][0] *= sc0; O[dt][1] *= sc0;
            O[dt][2] *= sc1; O[dt][3] *= sc1;
        }

        // ---- O += P V (2-pass: P hi/lo x single-fp16 V) ----
#pragma unroll
        for (int kc = 0; kc < 4; kc++) {
            uint32_t pah[4], pal[4];
            split2h(S[2 * kc][0],     S[2 * kc][1],     pah[0], pal[0]);
            split2h(S[2 * kc][2],     S[2 * kc][3],     pah[1], pal[1]);
            split2h(S[2 * kc + 1][0], S[2 * kc + 1][1], pah[2], pal[2]);
            split2h(S[2 * kc + 1][2], S[2 * kc + 1][3], pah[3], pal[3]);
#pragma unroll
            for (int db = 0; db < 4; db++) {
                uint32_t vh[4];
                int trow = kc * 16 + (li & 1) * 8 + lr;
                int dcb = (db * 16 + (li >> 1) * 8) * 2;
                uint32_t off = sw128((uint32_t)(trow * 128 + dcb));
                ldsm4t(vh[0], vh[1], vh[2], vh[3], sb + OFF_V + off);
#pragma unroll
                for (int od = 0; od < 2; od++) {
                    float* c = O[db * 2 + od];
                    mma16816(c, pah, vh[2 * od], vh[2 * od + 1]);
                    mma16816(c, pal, vh[2 * od], vh[2 * od + 1]);
                }
            }
        }
    }

    // ---- epilogue: vals[b, s, (7-h)*64+d] as single fp16 ----
    const float inv0 = 1.f / l0, inv1 = 1.f / l1;
    const int colbase = (HH - 1 - h) * DD;
#pragma unroll
    for (int dt = 0; dt < 8; dt++) {
        int d = dt * 8 + 2 * tig;
        size_t i0 = ((size_t)(b * SS + qg0)) * EE + colbase + d;
        size_t i1 = ((size_t)(b * SS + qg1)) * EE + colbase + d;
        *(uint32_t*)(g_Av + i0) = packh2(O[dt][0] * inv0, O[dt][1] * inv0);
        *(uint32_t*)(g_Av + i1) = packh2(O[dt][2] * inv1, O[dt][3] * inv1);
    }
}

// ---------------------------------------------------------------------------
// LayerNorm per row of 512.
// ---------------------------------------------------------------------------
__global__ void ln_kernel(const float* __restrict__ gamma,
                          const float* __restrict__ beta,
                          float* __restrict__ out) {
    const int row = blockIdx.x;
    const float* v = g_proj + (size_t)row * EE;
    const int t = threadIdx.x;

    float a0 = v[t], a1 = v[t + 256];
    float s = a0 + a1;
    float q = a0 * a0 + a1 * a1;

#pragma unroll
    for (int off = 16; off; off >>= 1) {
        s += __shfl_xor_sync(0xffffffffu, s, off);
        q += __shfl_xor_sync(0xffffffffu, q, off);
    }
    __shared__ float ss[8], sq[8];
    int w = t >> 5, lane = t & 31;
    if (lane == 0) { ss[w] = s; sq[w] = q; }
    __syncthreads();

    float S = 0.f, Q2 = 0.f;
#pragma unroll
    for (int i = 0; i < 8; i++) { S += ss[i]; Q2 += sq[i]; }

    float mu  = S * (1.f / EE);
    float var = Q2 * (1.f / EE) - mu * mu;
    float inv = rsqrtf(var + 1e-5f);

    out[(size_t)row * EE + t]       = (a0 - mu) * inv * gamma[t]       + beta[t];
    out[(size_t)row * EE + t + 256] = (a1 - mu) * inv * gamma[t + 256] + beta[t + 256];
}

// ---------------------------------------------------------------------------
extern "C" void kernel_launch(void* const* d_in, const int* in_sizes, int n_in,
                              void* d_out, int out_size) {
    const float* x     = (const float*)d_in[0];
    const float* Wq    = (const float*)d_in[1];
    const float* Wk    = (const float*)d_in[2];
    const float* Wv    = (const float*)d_in[3];
    const float* Wp    = (const float*)d_in[4];
    const float* bp    = (const float*)d_in[5];
    const float* gamma = (const float*)d_in[6];
    const float* beta  = (const float*)d_in[7];
    float* out = (float*)d_out;

    cudaFuncSetAttribute(gemm_mma_kernel, cudaFuncAttributeMaxDynamicSharedMemorySize, GEMM_SMEM);
    cudaFuncSetAttribute(attn_mma_kernel, cudaFuncAttributeMaxDynamicSharedMemorySize, ATTN_SMEM);

    prep_all_kernel<<<PREP_BLOCKS, 256>>>(Wq, Wk, Wv, Wp, x);

    gemm_mma_kernel<<<dim3(MM / 128, 12), 256, GEMM_SMEM>>>(0, x, bp);
    attn_mma_kernel<<<256, 256, ATTN_SMEM>>>();
    gemm_mma_kernel<<<dim3(MM / 128, 4), 256, GEMM_SMEM>>>(1, x, bp);
    ln_kernel<<<MM, 256>>>(gamma, beta, out);
}

// round 10
// speedup vs baseline: 1.0324x; 1.0324x over previous
#include <cuda_runtime.h>
#include <cuda_fp16.h>
#include <math.h>
#include <stdint.h>

// Problem constants
#define BB 2
#define SS 2048
#define EE 512
#define HH 8
#define DD 64
#define MM (BB * SS)   // 4096 rows

// Scratch (device globals; no allocation allowed)
__device__ float g_proj[MM * EE];

// fp16 operand arrays
__device__ __align__(16) __half g_Ax_hi[MM * EE];       // x split (qkv gemm A)
__device__ __align__(16) __half g_Ax_lo[MM * EE];
__device__ __align__(16) __half g_Qh[16 * 2048 * 64];   // [bh][s][d]
__device__ __align__(16) __half g_Ql[16 * 2048 * 64];
__device__ __align__(16) __half g_Kh[16 * 2048 * 64];
__device__ __align__(16) __half g_Kl[16 * 2048 * 64];
__device__ __align__(16) __half g_Vh[16 * 2048 * 64];   // single fp16
__device__ __align__(16) __half g_Av[MM * EE];          // attention out, single fp16
__device__ __align__(16) __half g_Bqkv_hi[3 * EE * EE]; // [n=z*512+h*64+d][e]
__device__ __align__(16) __half g_Bqkv_lo[3 * EE * EE];
__device__ __align__(16) __half g_Bp_hi[EE * EE];       // [n][k] = Wp[n][k]
__device__ __align__(16) __half g_Bp_lo[EE * EE];

// ---------------------------------------------------------------------------
// helpers
// ---------------------------------------------------------------------------
__device__ __forceinline__ uint32_t smem_u32(const void* p) {
    uint32_t a;
    asm("{ .reg .u64 t; cvta.to.shared.u64 t, %1; cvt.u32.u64 %0, t; }"
        : "=r"(a) : "l"(p));
    return a;
}
__device__ __forceinline__ uint32_t sw128(uint32_t off) {
    return off ^ ((off >> 3) & 0x70);
}
__device__ __forceinline__ void cpasync16(uint32_t dst, const void* src) {
    asm volatile("cp.async.cg.shared.global [%0], [%1], 16;"
                 :: "r"(dst), "l"(src) : "memory");
}
template <int N>
__device__ __forceinline__ void waitg() {
    asm volatile("cp.async.wait_group %0;" :: "n"(N) : "memory");
}
__device__ __forceinline__ void commitg() {
    asm volatile("cp.async.commit_group;" ::: "memory");
}
__device__ __forceinline__ void ldsm4(uint32_t& r0, uint32_t& r1, uint32_t& r2,
                                      uint32_t& r3, uint32_t a) {
    asm volatile("ldmatrix.sync.aligned.m8n8.x4.shared.b16 {%0,%1,%2,%3}, [%4];"
                 : "=r"(r0), "=r"(r1), "=r"(r2), "=r"(r3) : "r"(a));
}
__device__ __forceinline__ void ldsm4t(uint32_t& r0, uint32_t& r1, uint32_t& r2,
                                       uint32_t& r3, uint32_t a) {
    asm volatile("ldmatrix.sync.aligned.m8n8.x4.trans.shared.b16 {%0,%1,%2,%3}, [%4];"
                 : "=r"(r0), "=r"(r1), "=r"(r2), "=r"(r3) : "r"(a));
}
// fp32-accumulator HMMA (main pass)
__device__ __forceinline__ void mma16816(float* c, const uint32_t* a,
                                         uint32_t b0, uint32_t b1) {
    asm volatile(
        "mma.sync.aligned.m16n8k16.row.col.f32.f16.f16.f32 "
        "{%0,%1,%2,%3}, {%4,%5,%6,%7}, {%8,%9}, {%0,%1,%2,%3};"
        : "+f"(c[0]), "+f"(c[1]), "+f"(c[2]), "+f"(c[3])
        : "r"(a[0]), "r"(a[1]), "r"(a[2]), "r"(a[3]), "r"(b0), "r"(b1));
}
// fp16-accumulator HMMA (residual passes; small magnitudes)
__device__ __forceinline__ void mma16816h(uint32_t* c, const uint32_t* a,
                                          uint32_t b0, uint32_t b1) {
    asm volatile(
        "mma.sync.aligned.m16n8k16.row.col.f16.f16.f16.f16 "
        "{%0,%1}, {%2,%3,%4,%5}, {%6,%7}, {%0,%1};"
        : "+r"(c[0]), "+r"(c[1])
        : "r"(a[0]), "r"(a[1]), "r"(a[2]), "r"(a[3]), "r"(b0), "r"(b1));
}
__device__ __forceinline__ float2 h2f2(uint32_t h) {
    __half2 v = *reinterpret_cast<__half2*>(&h);
    return __half22float2(v);
}
__device__ __forceinline__ uint32_t packh2(float a, float b) {
    __half ha = __float2half_rn(a), hb = __float2half_rn(b);
    return (uint32_t)__half_as_ushort(ha) |
           ((uint32_t)__half_as_ushort(hb) << 16);
}
__device__ __forceinline__ void split2h(float a, float b, uint32_t& hi, uint32_t& lo) {
    __half ha = __float2half_rn(a), hb = __float2half_rn(b);
    float ra = a - __half2float(ha), rb = b - __half2float(hb);
    hi = (uint32_t)__half_as_ushort(ha) |
         ((uint32_t)__half_as_ushort(hb) << 16);
    __half la = __float2half_rn(ra), lb = __float2half_rn(rb);
    lo = (uint32_t)__half_as_ushort(la) |
         ((uint32_t)__half_as_ushort(lb) << 16);
}

// ---------------------------------------------------------------------------
// Merged prep: wqkv hi/lo, wp hi/lo, x hi/lo in ONE launch.
// ---------------------------------------------------------------------------
#define N_WQKV (3 * EE * EE)            // 786432
#define N_WP   (EE * EE)                // 262144
#define N_X    (MM * EE)                // 2097152
__global__ void prep_all_kernel(const float* __restrict__ Wq,
                                const float* __restrict__ Wk,
                                const float* __restrict__ Wv,
                                const float* __restrict__ Wp,
                                const float* __restrict__ x) {
    int idx = blockIdx.x * 256 + threadIdx.x;
    if (idx < N_WQKV) {
        int n = idx >> 9, e = idx & 511;
        int z = n >> 9, h = (n >> 6) & 7, d = n & 63;
        const float* W = (z == 0) ? Wq : ((z == 1) ? Wk : Wv);
        float v = W[((size_t)h * EE + e) * DD + d];
        __half hi = __float2half_rn(v);
        g_Bqkv_hi[idx] = hi;
        g_Bqkv_lo[idx] = __float2half_rn(v - __half2float(hi));
    } else if (idx < N_WQKV + N_WP) {
        int i = idx - N_WQKV;
        float v = Wp[i];
        __half hi = __float2half_rn(v);
        g_Bp_hi[i] = hi;
        g_Bp_lo[i] = __float2half_rn(v - __half2float(hi));
    } else {
        int i = idx - N_WQKV - N_WP;
        float v = x[i];
        __half hi = __float2half_rn(v);
        g_Ax_hi[i] = hi;
        g_Ax_lo[i] = __float2half_rn(v - __half2float(hi));
    }
}
#define PREP_BLOCKS ((N_WQKV + N_WP + N_X) / 256)

// ---------------------------------------------------------------------------
// mma.sync GEMM: C[128 x 128] tile of A[M x 512] * B[N x 512]^T
// Main pass (Ah·Bh) fp32 accum; residual passes (Ah·Bl, Al·Bh) share a
// fp16 accumulator (magnitudes ~5e-4, safe).
// mode 0: qkv (N=1536) -> Q/K hi/lo fp16, V single fp16.
// mode 1: proj (N=512), A = g_Av single fp16 (no Al pass) -> g_proj.
// 256 threads = 8 warps (4m x 2n). 3-stage cp.async pipeline (k=64).
// ---------------------------------------------------------------------------
#define STAGE_BYTES 65536
#define GEMM_SMEM (3 * STAGE_BYTES)   // 196608

__global__ __launch_bounds__(256, 1)
void gemm_mma_kernel(int mode, const float* __restrict__ x,
                     const float* __restrict__ bp) {
    extern __shared__ char sm[];
    const uint32_t smb = smem_u32(sm);
    const int t = threadIdx.x;
    const int w = t >> 5, l = t & 31;
    const int wm = w & 3, wn = w >> 2;
    const int gid = l >> 2, tig = l & 3;
    const int m0 = blockIdx.x * 128;
    const int n0 = blockIdx.y * 128;

    const bool useAl = (mode == 0);

    const __half* Ah_g = (mode == 0) ? g_Ax_hi : g_Av;
    const __half* Al_g = g_Ax_lo;
    const __half* Bh_g = (mode == 0) ? g_Bqkv_hi : g_Bp_hi;
    const __half* Bl_g = (mode == 0) ? g_Bqkv_lo : g_Bp_lo;

    float acc[2][8][4];
    uint32_t acch[2][8][2];
#pragma unroll
    for (int i = 0; i < 2; i++)
#pragma unroll
        for (int j = 0; j < 8; j++) {
#pragma unroll
            for (int c = 0; c < 4; c++) acc[i][j][c] = 0.f;
            acch[i][j][0] = 0u; acch[i][j][1] = 0u;
        }

    auto issue_stage = [&](int s) {
        const int k0 = s * 64;
        const uint32_t sb = smb + (s % 3) * STAGE_BYTES;
        const __half* gsrc[4] = {Ah_g, Al_g, Bh_g, Bl_g};
#pragma unroll
        for (int tl = 0; tl < 4; tl++) {
            if (tl == 1 && !useAl) continue;
            const uint32_t tbase = sb + tl * 16384;
            const __half* g = gsrc[tl];
            const int rbase = (tl < 2) ? m0 : n0;
#pragma unroll
            for (int i = 0; i < 4; i++) {
                int c = t + 256 * i;
                int row = c >> 3, cb = c & 7;
                uint32_t dst = tbase + sw128((uint32_t)(row * 128 + cb * 16));
                const __half* src =
                    g + (size_t)(rbase + row) * EE + k0 + cb * 8;
                cpasync16(dst, src);
            }
        }
        commitg();
    };

    issue_stage(0);
    issue_stage(1);

    const int li = l >> 3;
    const int lr = l & 7;

    for (int s = 0; s < 8; s++) {
        if (s < 7) waitg<1>(); else waitg<0>();
        __syncthreads();
        if (s + 2 < 8) issue_stage(s + 2);

        const uint32_t sb = smb + (s % 3) * STAGE_BYTES;

#pragma unroll
        for (int kk = 0; kk < 4; kk++) {
            uint32_t ah[2][4], al[2][4];
#pragma unroll
            for (int mt = 0; mt < 2; mt++) {
                int row = wm * 32 + mt * 16 + (li & 1) * 8 + lr;
                int cb = kk * 2 + (li >> 1);
                uint32_t off = sw128((uint32_t)(row * 128 + cb * 16));
                ldsm4(ah[mt][0], ah[mt][1], ah[mt][2], ah[mt][3], sb + off);
                if (useAl)
                    ldsm4(al[mt][0], al[mt][1], al[mt][2], al[mt][3],
                          sb + 16384 + off);
            }
#pragma unroll
            for (int h2 = 0; h2 < 2; h2++) {
                uint32_t bh[2][4], bl[2][4];
#pragma unroll
                for (int p2 = 0; p2 < 2; p2++) {
                    int ntb = h2 * 2 + p2;
                    int nrow = wn * 64 + ntb * 16 + (li >> 1) * 8 + lr;
                    int cb = kk * 2 + (li & 1);
                    uint32_t off = sw128((uint32_t)(nrow * 128 + cb * 16));
                    ldsm4(bh[p2][0], bh[p2][1], bh[p2][2], bh[p2][3],
                          sb + 32768 + off);
                    ldsm4(bl[p2][0], bl[p2][1], bl[p2][2], bl[p2][3],
                          sb + 49152 + off);
                }
#pragma unroll
                for (int mt = 0; mt < 2; mt++)
#pragma unroll
                    for (int q = 0; q < 4; q++) {
                        int nt = h2 * 4 + q;
                        int p2 = q >> 1, od = q & 1;
                        mma16816(acc[mt][nt], ah[mt],
                                 bh[p2][2 * od], bh[p2][2 * od + 1]);
                        mma16816h(acch[mt][nt], ah[mt],
                                  bl[p2][2 * od], bl[p2][2 * od + 1]);
                        if (useAl)
                            mma16816h(acch[mt][nt], al[mt],
                                      bh[p2][2 * od], bh[p2][2 * od + 1]);
                    }
            }
        }
    }

    // ---- fold fp16 residual accumulators into fp32 ----
#pragma unroll
    for (int mt = 0; mt < 2; mt++)
#pragma unroll
        for (int nt = 0; nt < 8; nt++) {
            float2 r0 = h2f2(acch[mt][nt][0]);
            float2 r1 = h2f2(acch[mt][nt][1]);
            acc[mt][nt][0] += r0.x; acc[mt][nt][1] += r0.y;
            acc[mt][nt][2] += r1.x; acc[mt][nt][3] += r1.y;
        }

    // ---- epilogue ----
    const int row0 = m0 + wm * 32 + gid;
    if (mode == 0) {
#pragma unroll
        for (int mt = 0; mt < 2; mt++) {
            int rg = row0 + mt * 16;
            int b = rg >> 11, sI = rg & 2047;
#pragma unroll
            for (int nt = 0; nt < 8; nt++) {
                int ng = n0 + wn * 64 + nt * 8 + 2 * tig;
                int z = ng >> 9, r9 = ng & 511;
                int h = r9 >> 6, d = r9 & 63;
                size_t base = (((size_t)(b * HH + h)) * SS + sI) * DD + d;
                if (z == 2) {
                    *(uint32_t*)(g_Vh + base) =
                        packh2(acc[mt][nt][0], acc[mt][nt][1]);
                    *(uint32_t*)(g_Vh + base + 8 * DD) =
                        packh2(acc[mt][nt][2], acc[mt][nt][3]);
                } else {
                    __half* oh = (z == 0) ? g_Qh : g_Kh;
                    __half* ol = (z == 0) ? g_Ql : g_Kl;
                    uint32_t hi, lo;
                    split2h(acc[mt][nt][0], acc[mt][nt][1], hi, lo);
                    *(uint32_t*)(oh + base) = hi;
                    *(uint32_t*)(ol + base) = lo;
                    split2h(acc[mt][nt][2], acc[mt][nt][3], hi, lo);
                    *(uint32_t*)(oh + base + 8 * DD) = hi;
                    *(uint32_t*)(ol + base + 8 * DD) = lo;
                }
            }
        }
    } else {
#pragma unroll
        for (int mt = 0; mt < 2; mt++) {
            int rg = row0 + mt * 16;
#pragma unroll
            for (int nt = 0; nt < 8; nt++) {
                int ng = n0 + wn * 64 + nt * 8 + 2 * tig;
                float2 bpv = *(const float2*)(bp + ng);
                float2 x0 = *(const float2*)(x + (size_t)rg * EE + ng);
                float2 x1 = *(const float2*)(x + (size_t)(rg + 8) * EE + ng);
                *(float2*)(g_proj + (size_t)rg * EE + ng) =
                    make_float2(acc[mt][nt][0] + bpv.x + x0.x,
                                acc[mt][nt][1] + bpv.y + x0.y);
                *(float2*)(g_proj + (size_t)(rg + 8) * EE + ng) =
                    make_float2(acc[mt][nt][2] + bpv.x + x1.x,
                                acc[mt][nt][3] + bpv.y + x1.y);
            }
        }
    }
}

// ---------------------------------------------------------------------------
// Flash attention: QK^T main pass fp32-acc + residuals in shared fp16-acc;
// PV main pass fp32-acc + Pl·V per-tile fp16-acc. q-tile 128 rows,
// k-tiles of 64, 8 warps, 3-stage pipeline, warp-level masked-tile skip.
// ---------------------------------------------------------------------------
#define NEG_BIG (-1e30f)
#define SM_QH 0
#define SM_QL 16384
#define SM_STG 32768
#define STG_SZ 24576          // Kh 8K + Kl 8K + V 8K
#define OFF_KH 0
#define OFF_KL 8192
#define OFF_V 16384
#define ATTN_SMEM (SM_STG + 3 * STG_SZ)   // 106496

__global__ __launch_bounds__(256, 1)
void attn_mma_kernel() {
    extern __shared__ char sm[];
    const uint32_t smb = smem_u32(sm);
    const int t = threadIdx.x;
    const int w = t >> 5, l = t & 31;
    const int gid = l >> 2, tig = l & 3;
    const int li = l >> 3, lr = l & 7;

    const int bid = blockIdx.x;
    const int bh = bid & 15;
    const int qt = 15 - (bid >> 4);       // heavy tiles first
    const int b = bh >> 3, h = bh & 7;
    const int qs = qt * 128;
    const size_t bhoff = (size_t)bh * SS * DD;
    const int ktmax = 2 * qt + 1;

    // ---- issue Q (128x64 hi+lo); joins commit group of stage 0 ----
#pragma unroll
    for (int arr = 0; arr < 2; arr++) {
        const __half* g = arr ? g_Ql : g_Qh;
        uint32_t base = smb + (arr ? SM_QL : SM_QH);
#pragma unroll
        for (int i = 0; i < 4; i++) {
            int c = t + 256 * i;
            int row = c >> 3, cb = c & 7;
            cpasync16(base + sw128((uint32_t)(row * 128 + cb * 16)),
                      g + bhoff + (size_t)(qs + row) * DD + cb * 8);
        }
    }

    auto issue_stage = [&](int kt) {
        const uint32_t sb = smb + SM_STG + (kt % 3) * STG_SZ;
        const __half* gs[3] = {g_Kh, g_Kl, g_Vh};
        const int ks = kt * 64;
#pragma unroll
        for (int arr = 0; arr < 3; arr++) {
#pragma unroll
            for (int i = 0; i < 2; i++) {
                int c = t + 256 * i;
                int row = c >> 3, cb = c & 7;
                cpasync16(sb + arr * 8192 + sw128((uint32_t)(row * 128 + cb * 16)),
                          gs[arr] + bhoff + (size_t)(ks + row) * DD + cb * 8);
            }
        }
        commitg();
    };

    issue_stage(0);
    issue_stage(1);

    float O[8][4];
#pragma unroll
    for (int i = 0; i < 8; i++)
#pragma unroll
        for (int j = 0; j < 4; j++) O[i][j] = 0.f;
    float m0 = NEG_BIG, m1 = NEG_BIG, l0 = 0.f, l1 = 0.f;

    const int rowstrip = qs + w * 16;
    const int qg0 = rowstrip + gid;
    const int qg1 = qg0 + 8;

    for (int kt = 0; kt <= ktmax; kt++) {
        if (kt < ktmax) waitg<1>(); else waitg<0>();
        __syncthreads();
        if (kt + 2 <= ktmax) issue_stage(kt + 2);

        const uint32_t sb = smb + SM_STG + (kt % 3) * STG_SZ;
        const int ks = kt * 64;

        // warp-uniform skip: this warp's 16-row strip fully masked
        if (ks > rowstrip + 15) continue;

        // ---- S = Q K^T (hi·hi fp32; hi·lo + lo·hi shared fp16 acc) ----
        float S[8][4];
        uint32_t Sh[8][2];
#pragma unroll
        for (int i = 0; i < 8; i++) {
#pragma unroll
            for (int j = 0; j < 4; j++) S[i][j] = 0.f;
            Sh[i][0] = 0u; Sh[i][1] = 0u;
        }

#pragma unroll
        for (int kk = 0; kk < 4; kk++) {
            uint32_t qh[4], ql[4];
            {
                int row = w * 16 + (li & 1) * 8 + lr;
                int cb = kk * 2 + (li >> 1);
                uint32_t off = sw128((uint32_t)(row * 128 + cb * 16));
                ldsm4(qh[0], qh[1], qh[2], qh[3], smb + SM_QH + off);
                ldsm4(ql[0], ql[1], ql[2], ql[3], smb + SM_QL + off);
            }
#pragma unroll
            for (int nb = 0; nb < 4; nb++) {
                uint32_t kh[4], kl[4];
                int nrow = nb * 16 + (li >> 1) * 8 + lr;
                int cb = kk * 2 + (li & 1);
                uint32_t off = sw128((uint32_t)(nrow * 128 + cb * 16));
                ldsm4(kh[0], kh[1], kh[2], kh[3], sb + OFF_KH + off);
                ldsm4(kl[0], kl[1], kl[2], kl[3], sb + OFF_KL + off);
#pragma unroll
                for (int od = 0; od < 2; od++) {
                    mma16816(S[nb * 2 + od], qh, kh[2 * od], kh[2 * od + 1]);
                    mma16816h(Sh[nb * 2 + od], qh, kl[2 * od], kl[2 * od + 1]);
                    mma16816h(Sh[nb * 2 + od], ql, kh[2 * od], kh[2 * od + 1]);
                }
            }
        }
        // fold residuals
#pragma unroll
        for (int nt = 0; nt < 8; nt++) {
            float2 r0 = h2f2(Sh[nt][0]);
            float2 r1 = h2f2(Sh[nt][1]);
            S[nt][0] += r0.x; S[nt][1] += r0.y;
            S[nt][2] += r1.x; S[nt][3] += r1.y;
        }

        // ---- causal mask ----
        if (ks + 63 > rowstrip) {
#pragma unroll
            for (int nt = 0; nt < 8; nt++) {
                int c0 = ks + nt * 8 + 2 * tig;
                if (c0 > qg0) S[nt][0] = NEG_BIG;
                if (c0 + 1 > qg0) S[nt][1] = NEG_BIG;
                if (c0 > qg1) S[nt][2] = NEG_BIG;
                if (c0 + 1 > qg1) S[nt][3] = NEG_BIG;
            }
        }

        // ---- online softmax ----
        float mx0 = NEG_BIG, mx1 = NEG_BIG;
#pragma unroll
        for (int nt = 0; nt < 8; nt++) {
            mx0 = fmaxf(mx0, fmaxf(S[nt][0], S[nt][1]));
            mx1 = fmaxf(mx1, fmaxf(S[nt][2], S[nt][3]));
        }
        mx0 = fmaxf(mx0, __shfl_xor_sync(0xffffffffu, mx0, 1));
        mx0 = fmaxf(mx0, __shfl_xor_sync(0xffffffffu, mx0, 2));
        mx1 = fmaxf(mx1, __shfl_xor_sync(0xffffffffu, mx1, 1));
        mx1 = fmaxf(mx1, __shfl_xor_sync(0xffffffffu, mx1, 2));

        float mn0 = fmaxf(m0, mx0), mn1 = fmaxf(m1, mx1);
        float sc0 = __expf(m0 - mn0), sc1 = __expf(m1 - mn1);
        float rs0 = 0.f, rs1 = 0.f;
#pragma unroll
        for (int nt = 0; nt < 8; nt++) {
            S[nt][0] = __expf(S[nt][0] - mn0);
            S[nt][1] = __expf(S[nt][1] - mn0);
            S[nt][2] = __expf(S[nt][2] - mn1);
            S[nt][3] = __expf(S[nt][3] - mn1);
            rs0 += S[nt][0] + S[nt][1];
            rs1 += S[nt][2] + S[nt][3];
        }
        rs0 += __shfl_xor_sync(0xffffffffu, rs0, 1);
        rs0 += __shfl_xor_sync(0xffffffffu, rs0, 2);
        rs1 += __shfl_xor_sync(0xffffffffu, rs1, 1);
        rs1 += __shfl_xor_sync(0xffffffffu, rs1, 2);
        l0 = l0 * sc0 + rs0;
        l1 = l1 * sc1 + rs1;
        m0 = mn0; m1 = mn1;
#pragma unroll
        for (int dt = 0; dt < 8; dt++) {
            O[dt][0] *= sc0; O[dt][1] *= sc0;
            O[dt][2] *= sc1; O[dt][3] *= sc1;
        }

        // ---- O += P V (Ph·V fp32; Pl·V per-tile fp16 acc) ----
        uint32_t Oh[8][2];
#pragma unroll
        for (int i = 0; i < 8; i++) { Oh[i][0] = 0u; Oh[i][1] = 0u; }

#pragma unroll
        for (int kc = 0; kc < 4; kc++) {
            uint32_t pah[4], pal[4];
            split2h(S[2 * kc][0],     S[2 * kc][1],     pah[0], pal[0]);
            split2h(S[2 * kc][2],     S[2 * kc][3],     pah[1], pal[1]);
            split2h(S[2 * kc + 1][0], S[2 * kc + 1][1], pah[2], pal[2]);
            split2h(S[2 * kc + 1][2], S[2 * kc + 1][3], pah[3], pal[3]);
#pragma unroll
            for (int db = 0; db < 4; db++) {
                uint32_t vh[4];
                int trow = kc * 16 + (li & 1) * 8 + lr;
                int dcb = (db * 16 + (li >> 1) * 8) * 2;
                uint32_t off = sw128((uint32_t)(trow * 128 + dcb));
                ldsm4t(vh[0], vh[1], vh[2], vh[3], sb + OFF_V + off);
#pragma unroll
                for (int od = 0; od < 2; od++) {
                    mma16816(O[db * 2 + od], pah, vh[2 * od], vh[2 * od + 1]);
                    mma16816h(Oh[db * 2 + od], pal, vh[2 * od], vh[2 * od + 1]);
                }
            }
        }
        // fold PV residual
#pragma unroll
        for (int dt = 0; dt < 8; dt++) {
            float2 r0 = h2f2(Oh[dt][0]);
            float2 r1 = h2f2(Oh[dt][1]);
            O[dt][0] += r0.x; O[dt][1] += r0.y;
            O[dt][2] += r1.x; O[dt][3] += r1.y;
        }
    }

    // ---- epilogue: vals[b, s, (7-h)*64+d] as single fp16 ----
    const float inv0 = 1.f / l0, inv1 = 1.f / l1;
    const int colbase = (HH - 1 - h) * DD;
#pragma unroll
    for (int dt = 0; dt < 8; dt++) {
        int d = dt * 8 + 2 * tig;
        size_t i0 = ((size_t)(b * SS + qg0)) * EE + colbase + d;
        size_t i1 = ((size_t)(b * SS + qg1)) * EE + colbase + d;
        *(uint32_t*)(g_Av + i0) = packh2(O[dt][0] * inv0, O[dt][1] * inv0);
        *(uint32_t*)(g_Av + i1) = packh2(O[dt][2] * inv1, O[dt][3] * inv1);
    }
}

// ---------------------------------------------------------------------------
// LayerNorm per row of 512.
// ---------------------------------------------------------------------------
__global__ void ln_kernel(const float* __restrict__ gamma,
                          const float* __restrict__ beta,
                          float* __restrict__ out) {
    const int row = blockIdx.x;
    const float* v = g_proj + (size_t)row * EE;
    const int t = threadIdx.x;

    float a0 = v[t], a1 = v[t + 256];
    float s = a0 + a1;
    float q = a0 * a0 + a1 * a1;

#pragma unroll
    for (int off = 16; off; off >>= 1) {
        s += __shfl_xor_sync(0xffffffffu, s, off);
        q += __shfl_xor_sync(0xffffffffu, q, off);
    }
    __shared__ float ss[8], sq[8];
    int w = t >> 5, lane = t & 31;
    if (lane == 0) { ss[w] = s; sq[w] = q; }
    __syncthreads();

    float S = 0.f, Q2 = 0.f;
#pragma unroll
    for (int i = 0; i < 8; i++) { S += ss[i]; Q2 += sq[i]; }

    float mu  = S * (1.f / EE);
    float var = Q2 * (1.f / EE) - mu * mu;
    float inv = rsqrtf(var + 1e-5f);

    out[(size_t)row * EE + t]       = (a0 - mu) * inv * gamma[t]       + beta[t];
    out[(size_t)row * EE + t + 256] = (a1 - mu) * inv * gamma[t + 256] + beta[t + 256];
}

// ---------------------------------------------------------------------------
extern "C" void kernel_launch(void* const* d_in, const int* in_sizes, int n_in,
                              void* d_out, int out_size) {
    const float* x     = (const float*)d_in[0];
    const float* Wq    = (const float*)d_in[1];
    const float* Wk    = (const float*)d_in[2];
    const float* Wv    = (const float*)d_in[3];
    const float* Wp    = (const float*)d_in[4];
    const float* bp    = (const float*)d_in[5];
    const float* gamma = (const float*)d_in[6];
    const float* beta  = (const float*)d_in[7];
    float* out = (float*)d_out;

    cudaFuncSetAttribute(gemm_mma_kernel, cudaFuncAttributeMaxDynamicSharedMemorySize, GEMM_SMEM);
    cudaFuncSetAttribute(attn_mma_kernel, cudaFuncAttributeMaxDynamicSharedMemorySize, ATTN_SMEM);

    prep_all_kernel<<<PREP_BLOCKS, 256>>>(Wq, Wk, Wv, Wp, x);

    gemm_mma_kernel<<<dim3(MM / 128, 12), 256, GEMM_SMEM>>>(0, x, bp);
    attn_mma_kernel<<<256, 256, ATTN_SMEM>>>();
    gemm_mma_kernel<<<dim3(MM / 128, 4), 256, GEMM_SMEM>>>(1, x, bp);
    ln_kernel<<<MM, 256>>>(gamma, beta, out);
}

// round 11
// speedup vs baseline: 1.1199x; 1.0848x over previous
#include <cuda_runtime.h>
#include <cuda_fp16.h>
#include <math.h>
#include <stdint.h>

// Problem constants
#define BB 2
#define SS 2048
#define EE 512
#define HH 8
#define DD 64
#define MM (BB * SS)   // 4096 rows

// Scratch (device globals; no allocation allowed)
__device__ float g_proj[MM * EE];

// fp16 operand arrays
__device__ __align__(16) __half g_Ax_hi[MM * EE];       // x split (qkv gemm A)
__device__ __align__(16) __half g_Ax_lo[MM * EE];
__device__ __align__(16) __half g_Qh[16 * 2048 * 64];   // [bh][s][d]
__device__ __align__(16) __half g_Ql[16 * 2048 * 64];
__device__ __align__(16) __half g_Kh[16 * 2048 * 64];
__device__ __align__(16) __half g_Kl[16 * 2048 * 64];
__device__ __align__(16) __half g_Vh[16 * 2048 * 64];   // single fp16
__device__ __align__(16) __half g_Av[MM * EE];          // attention out, single fp16
__device__ __align__(16) __half g_Bqkv_hi[3 * EE * EE]; // [n=z*512+h*64+d][e]
__device__ __align__(16) __half g_Bqkv_lo[3 * EE * EE];
__device__ __align__(16) __half g_Bp_hi[EE * EE];       // [n][k] = Wp[n][k]
__device__ __align__(16) __half g_Bp_lo[EE * EE];

// ---------------------------------------------------------------------------
// helpers
// ---------------------------------------------------------------------------
__device__ __forceinline__ uint32_t smem_u32(const void* p) {
    uint32_t a;
    asm("{ .reg .u64 t; cvta.to.shared.u64 t, %1; cvt.u32.u64 %0, t; }"
        : "=r"(a) : "l"(p));
    return a;
}
__device__ __forceinline__ uint32_t sw128(uint32_t off) {
    return off ^ ((off >> 3) & 0x70);
}
__device__ __forceinline__ void cpasync16(uint32_t dst, const void* src) {
    asm volatile("cp.async.cg.shared.global [%0], [%1], 16;"
                 :: "r"(dst), "l"(src) : "memory");
}
template <int N>
__device__ __forceinline__ void waitg() {
    asm volatile("cp.async.wait_group %0;" :: "n"(N) : "memory");
}
__device__ __forceinline__ void commitg() {
    asm volatile("cp.async.commit_group;" ::: "memory");
}
__device__ __forceinline__ void ldsm4(uint32_t& r0, uint32_t& r1, uint32_t& r2,
                                      uint32_t& r3, uint32_t a) {
    asm volatile("ldmatrix.sync.aligned.m8n8.x4.shared.b16 {%0,%1,%2,%3}, [%4];"
                 : "=r"(r0), "=r"(r1), "=r"(r2), "=r"(r3) : "r"(a));
}
__device__ __forceinline__ void ldsm4t(uint32_t& r0, uint32_t& r1, uint32_t& r2,
                                       uint32_t& r3, uint32_t a) {
    asm volatile("ldmatrix.sync.aligned.m8n8.x4.trans.shared.b16 {%0,%1,%2,%3}, [%4];"
                 : "=r"(r0), "=r"(r1), "=r"(r2), "=r"(r3) : "r"(a));
}
__device__ __forceinline__ void mma16816(float* c, const uint32_t* a,
                                         uint32_t b0, uint32_t b1) {
    asm volatile(
        "mma.sync.aligned.m16n8k16.row.col.f32.f16.f16.f32 "
        "{%0,%1,%2,%3}, {%4,%5,%6,%7}, {%8,%9}, {%0,%1,%2,%3};"
        : "+f"(c[0]), "+f"(c[1]), "+f"(c[2]), "+f"(c[3])
        : "r"(a[0]), "r"(a[1]), "r"(a[2]), "r"(a[3]), "r"(b0), "r"(b1));
}
__device__ __forceinline__ uint32_t packh2(float a, float b) {
    __half ha = __float2half_rn(a), hb = __float2half_rn(b);
    return (uint32_t)__half_as_ushort(ha) |
           ((uint32_t)__half_as_ushort(hb) << 16);
}
__device__ __forceinline__ void split2h(float a, float b, uint32_t& hi, uint32_t& lo) {
    __half ha = __float2half_rn(a), hb = __float2half_rn(b);
    float ra = a - __half2float(ha), rb = b - __half2float(hb);
    hi = (uint32_t)__half_as_ushort(ha) |
         ((uint32_t)__half_as_ushort(hb) << 16);
    __half la = __float2half_rn(ra), lb = __float2half_rn(rb);
    lo = (uint32_t)__half_as_ushort(la) |
         ((uint32_t)__half_as_ushort(lb) << 16);
}

// ---------------------------------------------------------------------------
// Merged, vectorized prep: wqkv hi/lo, wp hi/lo, x hi/lo — ONE launch,
// 4 elements per thread.
// ---------------------------------------------------------------------------
#define N_WQKV (3 * EE * EE)            // 786432
#define N_WP   (EE * EE)                // 262144
#define N_X    (MM * EE)                // 2097152
#define PREP_BLOCKS ((N_WQKV + N_WP + N_X) / 4 / 256)   // 3072

__global__ void prep_all_kernel(const float* __restrict__ Wq,
                                const float* __restrict__ Wk,
                                const float* __restrict__ Wv,
                                const float* __restrict__ Wp,
                                const float* __restrict__ x) {
    int idx = (blockIdx.x * 256 + threadIdx.x) * 4;
    if (idx < N_WQKV) {
        int n = idx >> 9, e0 = idx & 511;
        int z = n >> 9, h = (n >> 6) & 7, d = n & 63;
        const float* W = (z == 0) ? Wq : ((z == 1) ? Wk : Wv);
        uint32_t h0, l0, h1, l1;
        float v0 = W[((size_t)h * EE + e0 + 0) * DD + d];
        float v1 = W[((size_t)h * EE + e0 + 1) * DD + d];
        float v2 = W[((size_t)h * EE + e0 + 2) * DD + d];
        float v3 = W[((size_t)h * EE + e0 + 3) * DD + d];
        split2h(v0, v1, h0, l0);
        split2h(v2, v3, h1, l1);
        *(uint2*)(g_Bqkv_hi + idx) = make_uint2(h0, h1);
        *(uint2*)(g_Bqkv_lo + idx) = make_uint2(l0, l1);
    } else if (idx < N_WQKV + N_WP) {
        int i = idx - N_WQKV;
        float4 v = *(const float4*)(Wp + i);
        uint32_t h0, l0, h1, l1;
        split2h(v.x, v.y, h0, l0);
        split2h(v.z, v.w, h1, l1);
        *(uint2*)(g_Bp_hi + i) = make_uint2(h0, h1);
        *(uint2*)(g_Bp_lo + i) = make_uint2(l0, l1);
    } else {
        int i = idx - N_WQKV - N_WP;
        float4 v = *(const float4*)(x + i);
        uint32_t h0, l0, h1, l1;
        split2h(v.x, v.y, h0, l0);
        split2h(v.z, v.w, h1, l1);
        *(uint2*)(g_Ax_hi + i) = make_uint2(h0, h1);
        *(uint2*)(g_Ax_lo + i) = make_uint2(l0, l1);
    }
}

// ---------------------------------------------------------------------------
// mma.sync GEMM: C[128 x 128] tile of A[M x 512] * B[N x 512]^T. fp32 accum.
// mode 0: qkv (N=1536). Q/K tiles (y<8): 3-pass (AhBh+AhBl+AlBh) -> hi/lo.
//         V tiles (y>=8): 2-pass (AhBh+AlBh) -> single fp16.
// mode 1: proj (N=512), A = g_Av single fp16: 2-pass (AhBh+AhBl) -> g_proj.
// 256 threads = 8 warps (4m x 2n). 3-stage cp.async pipeline (k=64).
// ---------------------------------------------------------------------------
#define STAGE_BYTES 65536
#define GEMM_SMEM (3 * STAGE_BYTES)   // 196608

__global__ __launch_bounds__(256, 1)
void gemm_mma_kernel(int mode, const float* __restrict__ x,
                     const float* __restrict__ bp) {
    extern __shared__ char sm[];
    const uint32_t smb = smem_u32(sm);
    const int t = threadIdx.x;
    const int w = t >> 5, l = t & 31;
    const int wm = w & 3, wn = w >> 2;
    const int gid = l >> 2, tig = l & 3;
    const int m0 = blockIdx.x * 128;
    const int n0 = blockIdx.y * 128;

    const bool useAl = (mode == 0);                         // pass Al·Bh
    const bool useBl = (mode == 1) || (blockIdx.y < 8);     // pass Ah·Bl

    const __half* Ah_g = (mode == 0) ? g_Ax_hi : g_Av;
    const __half* Al_g = g_Ax_lo;
    const __half* Bh_g = (mode == 0) ? g_Bqkv_hi : g_Bp_hi;
    const __half* Bl_g = (mode == 0) ? g_Bqkv_lo : g_Bp_lo;

    float acc[2][8][4];
#pragma unroll
    for (int i = 0; i < 2; i++)
#pragma unroll
        for (int j = 0; j < 8; j++)
#pragma unroll
            for (int c = 0; c < 4; c++) acc[i][j][c] = 0.f;

    auto issue_stage = [&](int s) {
        const int k0 = s * 64;
        const uint32_t sb = smb + (s % 3) * STAGE_BYTES;
        const __half* gsrc[4] = {Ah_g, Al_g, Bh_g, Bl_g};
#pragma unroll
        for (int tl = 0; tl < 4; tl++) {
            if (tl == 1 && !useAl) continue;
            if (tl == 3 && !useBl) continue;
            const uint32_t tbase = sb + tl * 16384;
            const __half* g = gsrc[tl];
            const int rbase = (tl < 2) ? m0 : n0;
#pragma unroll
            for (int i = 0; i < 4; i++) {
                int c = t + 256 * i;
                int row = c >> 3, cb = c & 7;
                uint32_t dst = tbase + sw128((uint32_t)(row * 128 + cb * 16));
                const __half* src =
                    g + (size_t)(rbase + row) * EE + k0 + cb * 8;
                cpasync16(dst, src);
            }
        }
        commitg();
    };

    issue_stage(0);
    issue_stage(1);

    const int li = l >> 3;
    const int lr = l & 7;

    for (int s = 0; s < 8; s++) {
        if (s < 7) waitg<1>(); else waitg<0>();
        __syncthreads();
        if (s + 2 < 8) issue_stage(s + 2);

        const uint32_t sb = smb + (s % 3) * STAGE_BYTES;

#pragma unroll
        for (int kk = 0; kk < 4; kk++) {
            uint32_t ah[2][4], al[2][4];
#pragma unroll
            for (int mt = 0; mt < 2; mt++) {
                int row = wm * 32 + mt * 16 + (li & 1) * 8 + lr;
                int cb = kk * 2 + (li >> 1);
                uint32_t off = sw128((uint32_t)(row * 128 + cb * 16));
                ldsm4(ah[mt][0], ah[mt][1], ah[mt][2], ah[mt][3], sb + off);
                if (useAl)
                    ldsm4(al[mt][0], al[mt][1], al[mt][2], al[mt][3],
                          sb + 16384 + off);
            }
#pragma unroll
            for (int h2 = 0; h2 < 2; h2++) {
                uint32_t bh[2][4], bl[2][4];
#pragma unroll
                for (int p2 = 0; p2 < 2; p2++) {
                    int ntb = h2 * 2 + p2;
                    int nrow = wn * 64 + ntb * 16 + (li >> 1) * 8 + lr;
                    int cb = kk * 2 + (li & 1);
                    uint32_t off = sw128((uint32_t)(nrow * 128 + cb * 16));
                    ldsm4(bh[p2][0], bh[p2][1], bh[p2][2], bh[p2][3],
                          sb + 32768 + off);
                    if (useBl)
                        ldsm4(bl[p2][0], bl[p2][1], bl[p2][2], bl[p2][3],
                              sb + 49152 + off);
                }
#pragma unroll
                for (int mt = 0; mt < 2; mt++)
#pragma unroll
                    for (int q = 0; q < 4; q++) {
                        int nt = h2 * 4 + q;
                        int p2 = q >> 1, od = q & 1;
                        float* c = acc[mt][nt];
                        mma16816(c, ah[mt], bh[p2][2 * od], bh[p2][2 * od + 1]);
                        if (useBl)
                            mma16816(c, ah[mt], bl[p2][2 * od], bl[p2][2 * od + 1]);
                        if (useAl)
                            mma16816(c, al[mt], bh[p2][2 * od], bh[p2][2 * od + 1]);
                    }
            }
        }
    }

    // ---- epilogue ----
    const int row0 = m0 + wm * 32 + gid;
    if (mode == 0) {
#pragma unroll
        for (int mt = 0; mt < 2; mt++) {
            int rg = row0 + mt * 16;
            int b = rg >> 11, sI = rg & 2047;
#pragma unroll
            for (int nt = 0; nt < 8; nt++) {
                int ng = n0 + wn * 64 + nt * 8 + 2 * tig;
                int z = ng >> 9, r9 = ng & 511;
                int h = r9 >> 6, d = r9 & 63;
                size_t base = (((size_t)(b * HH + h)) * SS + sI) * DD + d;
                if (z == 2) {
                    *(uint32_t*)(g_Vh + base) =
                        packh2(acc[mt][nt][0], acc[mt][nt][1]);
                    *(uint32_t*)(g_Vh + base + 8 * DD) =
                        packh2(acc[mt][nt][2], acc[mt][nt][3]);
                } else {
                    __half* oh = (z == 0) ? g_Qh : g_Kh;
                    __half* ol = (z == 0) ? g_Ql : g_Kl;
                    uint32_t hi, lo;
                    split2h(acc[mt][nt][0], acc[mt][nt][1], hi, lo);
                    *(uint32_t*)(oh + base) = hi;
                    *(uint32_t*)(ol + base) = lo;
                    split2h(acc[mt][nt][2], acc[mt][nt][3], hi, lo);
                    *(uint32_t*)(oh + base + 8 * DD) = hi;
                    *(uint32_t*)(ol + base + 8 * DD) = lo;
                }
            }
        }
    } else {
#pragma unroll
        for (int mt = 0; mt < 2; mt++) {
            int rg = row0 + mt * 16;
#pragma unroll
            for (int nt = 0; nt < 8; nt++) {
                int ng = n0 + wn * 64 + nt * 8 + 2 * tig;
                float2 bpv = *(const float2*)(bp + ng);
                float2 x0 = *(const float2*)(x + (size_t)rg * EE + ng);
                float2 x1 = *(const float2*)(x + (size_t)(rg + 8) * EE + ng);
                *(float2*)(g_proj + (size_t)rg * EE + ng) =
                    make_float2(acc[mt][nt][0] + bpv.x + x0.x,
                                acc[mt][nt][1] + bpv.y + x0.y);
                *(float2*)(g_proj + (size_t)(rg + 8) * EE + ng) =
                    make_float2(acc[mt][nt][2] + bpv.x + x1.x,
                                acc[mt][nt][3] + bpv.y + x1.y);
            }
        }
    }
}

// ---------------------------------------------------------------------------
// Flash attention: fp16 mma, fp32 accum. QK^T 3-pass (Q,K hi/lo);
// PV 2-pass (P hi/lo, V single fp16). q-tile 128 rows, k-tiles of 64,
// 8 warps, 3-stage pipeline, warp-level masked-strip skip.
// ---------------------------------------------------------------------------
#define NEG_BIG (-1e30f)
#define SM_QH 0
#define SM_QL 16384
#define SM_STG 32768
#define STG_SZ 24576          // Kh 8K + Kl 8K + V 8K
#define OFF_KH 0
#define OFF_KL 8192
#define OFF_V 16384
#define ATTN_SMEM (SM_STG + 3 * STG_SZ)   // 106496

__global__ __launch_bounds__(256, 1)
void attn_mma_kernel() {
    extern __shared__ char sm[];
    const uint32_t smb = smem_u32(sm);
    const int t = threadIdx.x;
    const int w = t >> 5, l = t & 31;
    const int gid = l >> 2, tig = l & 3;
    const int li = l >> 3, lr = l & 7;

    const int bid = blockIdx.x;
    const int bh = bid & 15;
    const int qt = 15 - (bid >> 4);       // heavy tiles first
    const int b = bh >> 3, h = bh & 7;
    const int qs = qt * 128;
    const size_t bhoff = (size_t)bh * SS * DD;
    const int ktmax = 2 * qt + 1;

    // ---- issue Q (128x64 hi+lo); joins commit group of stage 0 ----
#pragma unroll
    for (int arr = 0; arr < 2; arr++) {
        const __half* g = arr ? g_Ql : g_Qh;
        uint32_t base = smb + (arr ? SM_QL : SM_QH);
#pragma unroll
        for (int i = 0; i < 4; i++) {
            int c = t + 256 * i;
            int row = c >> 3, cb = c & 7;
            cpasync16(base + sw128((uint32_t)(row * 128 + cb * 16)),
                      g + bhoff + (size_t)(qs + row) * DD + cb * 8);
        }
    }

    auto issue_stage = [&](int kt) {
        const uint32_t sb = smb + SM_STG + (kt % 3) * STG_SZ;
        const __half* gs[3] = {g_Kh, g_Kl, g_Vh};
        const int ks = kt * 64;
#pragma unroll
        for (int arr = 0; arr < 3; arr++) {
#pragma unroll
            for (int i = 0; i < 2; i++) {
                int c = t + 256 * i;
                int row = c >> 3, cb = c & 7;
                cpasync16(sb + arr * 8192 + sw128((uint32_t)(row * 128 + cb * 16)),
                          gs[arr] + bhoff + (size_t)(ks + row) * DD + cb * 8);
            }
        }
        commitg();
    };

    issue_stage(0);
    issue_stage(1);

    float O[8][4];
#pragma unroll
    for (int i = 0; i < 8; i++)
#pragma unroll
        for (int j = 0; j < 4; j++) O[i][j] = 0.f;
    float m0 = NEG_BIG, m1 = NEG_BIG, l0 = 0.f, l1 = 0.f;

    const int rowstrip = qs + w * 16;
    const int qg0 = rowstrip + gid;
    const int qg1 = qg0 + 8;

    for (int kt = 0; kt <= ktmax; kt++) {
        if (kt < ktmax) waitg<1>(); else waitg<0>();
        __syncthreads();
        if (kt + 2 <= ktmax) issue_stage(kt + 2);

        const uint32_t sb = smb + SM_STG + (kt % 3) * STG_SZ;
        const int ks = kt * 64;

        // warp-uniform skip: this warp's 16-row strip fully masked
        if (ks > rowstrip + 15) continue;

        // ---- S = Q K^T (3-pass fp16 hi/lo, fp32 acc) ----
        float S[8][4];
#pragma unroll
        for (int i = 0; i < 8; i++)
#pragma unroll
            for (int j = 0; j < 4; j++) S[i][j] = 0.f;

#pragma unroll
        for (int kk = 0; kk < 4; kk++) {
            uint32_t qh[4], ql[4];
            {
                int row = w * 16 + (li & 1) * 8 + lr;
                int cb = kk * 2 + (li >> 1);
                uint32_t off = sw128((uint32_t)(row * 128 + cb * 16));
                ldsm4(qh[0], qh[1], qh[2], qh[3], smb + SM_QH + off);
                ldsm4(ql[0], ql[1], ql[2], ql[3], smb + SM_QL + off);
            }
#pragma unroll
            for (int nb = 0; nb < 4; nb++) {
                uint32_t kh[4], kl[4];
                int nrow = nb * 16 + (li >> 1) * 8 + lr;
                int cb = kk * 2 + (li & 1);
                uint32_t off = sw128((uint32_t)(nrow * 128 + cb * 16));
                ldsm4(kh[0], kh[1], kh[2], kh[3], sb + OFF_KH + off);
                ldsm4(kl[0], kl[1], kl[2], kl[3], sb + OFF_KL + off);
#pragma unroll
                for (int od = 0; od < 2; od++) {
                    float* c = S[nb * 2 + od];
                    mma16816(c, qh, kh[2 * od], kh[2 * od + 1]);
                    mma16816(c, qh, kl[2 * od], kl[2 * od + 1]);
                    mma16816(c, ql, kh[2 * od], kh[2 * od + 1]);
                }
            }
        }

        // ---- causal mask ----
        if (ks + 63 > rowstrip) {
#pragma unroll
            for (int nt = 0; nt < 8; nt++) {
                int c0 = ks + nt * 8 + 2 * tig;
                if (c0 > qg0) S[nt][0] = NEG_BIG;
                if (c0 + 1 > qg0) S[nt][1] = NEG_BIG;
                if (c0 > qg1) S[nt][2] = NEG_BIG;
                if (c0 + 1 > qg1) S[nt][3] = NEG_BIG;
            }
        }

        // ---- online softmax ----
        float mx0 = NEG_BIG, mx1 = NEG_BIG;
#pragma unroll
        for (int nt = 0; nt < 8; nt++) {
            mx0 = fmaxf(mx0, fmaxf(S[nt][0], S[nt][1]));
            mx1 = fmaxf(mx1, fmaxf(S[nt][2], S[nt][3]));
        }
        mx0 = fmaxf(mx0, __shfl_xor_sync(0xffffffffu, mx0, 1));
        mx0 = fmaxf(mx0, __shfl_xor_sync(0xffffffffu, mx0, 2));
        mx1 = fmaxf(mx1, __shfl_xor_sync(0xffffffffu, mx1, 1));
        mx1 = fmaxf(mx1, __shfl_xor_sync(0xffffffffu, mx1, 2));

        float mn0 = fmaxf(m0, mx0), mn1 = fmaxf(m1, mx1);
        float sc0 = __expf(m0 - mn0), sc1 = __expf(m1 - mn1);
        float rs0 = 0.f, rs1 = 0.f;
#pragma unroll
        for (int nt = 0; nt < 8; nt++) {
            S[nt][0] = __expf(S[nt][0] - mn0);
            S[nt][1] = __expf(S[nt][1] - mn0);
            S[nt][2] = __expf(S[nt][2] - mn1);
            S[nt][3] = __expf(S[nt][3] - mn1);
            rs0 += S[nt][0] + S[nt][1];
            rs1 += S[nt][2] + S[nt][3];
        }
        rs0 += __shfl_xor_sync(0xffffffffu, rs0, 1);
        rs0 += __shfl_xor_sync(0xffffffffu, rs0, 2);
        rs1 += __shfl_xor_sync(0xffffffffu, rs1, 1);
        rs1 += __shfl_xor_sync(0xffffffffu, rs1, 2);
        l0 = l0 * sc0 + rs0;
        l1 = l1 * sc1 + rs1;
        m0 = mn0; m1 = mn1;
#pragma unroll
        for (int dt = 0; dt < 8; dt++) {
            O[dt][0] *= sc0; O[dt][1] *= sc0;
            O[dt][2] *= sc1; O[dt][3] *= sc1;
        }

        // ---- O += P V (2-pass: P hi/lo x single-fp16 V, fp32 acc) ----
#pragma unroll
        for (int kc = 0; kc < 4; kc++) {
            uint32_t pah[4], pal[4];
            split2h(S[2 * kc][0],     S[2 * kc][1],     pah[0], pal[0]);
            split2h(S[2 * kc][2],     S[2 * kc][3],     pah[1], pal[1]);
            split2h(S[2 * kc + 1][0], S[2 * kc + 1][1], pah[2], pal[2]);
            split2h(S[2 * kc + 1][2], S[2 * kc + 1][3], pah[3], pal[3]);
#pragma unroll
            for (int db = 0; db < 4; db++) {
                uint32_t vh[4];
                int trow = kc * 16 + (li & 1) * 8 + lr;
                int dcb = (db * 16 + (li >> 1) * 8) * 2;
                uint32_t off = sw128((uint32_t)(trow * 128 + dcb));
                ldsm4t(vh[0], vh[1], vh[2], vh[3], sb + OFF_V + off);
#pragma unroll
                for (int od = 0; od < 2; od++) {
                    float* c = O[db * 2 + od];
                    mma16816(c, pah, vh[2 * od], vh[2 * od + 1]);
                    mma16816(c, pal, vh[2 * od], vh[2 * od + 1]);
                }
            }
        }
    }

    // ---- epilogue: vals[b, s, (7-h)*64+d] as single fp16 ----
    const float inv0 = 1.f / l0, inv1 = 1.f / l1;
    const int colbase = (HH - 1 - h) * DD;
#pragma unroll
    for (int dt = 0; dt < 8; dt++) {
        int d = dt * 8 + 2 * tig;
        size_t i0 = ((size_t)(b * SS + qg0)) * EE + colbase + d;
        size_t i1 = ((size_t)(b * SS + qg1)) * EE + colbase + d;
        *(uint32_t*)(g_Av + i0) = packh2(O[dt][0] * inv0, O[dt][1] * inv0);
        *(uint32_t*)(g_Av + i1) = packh2(O[dt][2] * inv1, O[dt][3] * inv1);
    }
}

// ---------------------------------------------------------------------------
// LayerNorm per row of 512.
// ---------------------------------------------------------------------------
__global__ void ln_kernel(const float* __restrict__ gamma,
                          const float* __restrict__ beta,
                          float* __restrict__ out) {
    const int row = blockIdx.x;
    const float* v = g_proj + (size_t)row * EE;
    const int t = threadIdx.x;

    float a0 = v[t], a1 = v[t + 256];
    float s = a0 + a1;
    float q = a0 * a0 + a1 * a1;

#pragma unroll
    for (int off = 16; off; off >>= 1) {
        s += __shfl_xor_sync(0xffffffffu, s, off);
        q += __shfl_xor_sync(0xffffffffu, q, off);
    }
    __shared__ float ss[8], sq[8];
    int w = t >> 5, lane = t & 31;
    if (lane == 0) { ss[w] = s; sq[w] = q; }
    __syncthreads();

    float S = 0.f, Q2 = 0.f;
#pragma unroll
    for (int i = 0; i < 8; i++) { S += ss[i]; Q2 += sq[i]; }

    float mu  = S * (1.f / EE);
    float var = Q2 * (1.f / EE) - mu * mu;
    float inv = rsqrtf(var + 1e-5f);

    out[(size_t)row * EE + t]       = (a0 - mu) * inv * gamma[t]       + beta[t];
    out[(size_t)row * EE + t + 256] = (a1 - mu) * inv * gamma[t + 256] + beta[t + 256];
}

// ---------------------------------------------------------------------------
extern "C" void kernel_launch(void* const* d_in, const int* in_sizes, int n_in,
                              void* d_out, int out_size) {
    const float* x     = (const float*)d_in[0];
    const float* Wq    = (const float*)d_in[1];
    const float* Wk    = (const float*)d_in[2];
    const float* Wv    = (const float*)d_in[3];
    const float* Wp    = (const float*)d_in[4];
    const float* bp    = (const float*)d_in[5];
    const float* gamma = (const float*)d_in[6];
    const float* beta  = (const float*)d_in[7];
    float* out = (float*)d_out;

    cudaFuncSetAttribute(gemm_mma_kernel, cudaFuncAttributeMaxDynamicSharedMemorySize, GEMM_SMEM);
    cudaFuncSetAttribute(attn_mma_kernel, cudaFuncAttributeMaxDynamicSharedMemorySize, ATTN_SMEM);

    prep_all_kernel<<<PREP_BLOCKS, 256>>>(Wq, Wk, Wv, Wp, x);

    gemm_mma_kernel<<<dim3(MM / 128, 12), 256, GEMM_SMEM>>>(0, x, bp);
    attn_mma_kernel<<<256, 256, ATTN_SMEM>>>();
    gemm_mma_kernel<<<dim3(MM / 128, 4), 256, GEMM_SMEM>>>(1, x, bp);
    ln_kernel<<<MM, 256>>>(gamma, beta, out);
}

// round 12
// speedup vs baseline: 1.1948x; 1.0669x over previous
#include <cuda_runtime.h>
#include <cuda_fp16.h>
#include <math.h>
#include <stdint.h>

// Problem constants
#define BB 2
#define SS 2048
#define EE 512
#define HH 8
#define DD 64
#define MM (BB * SS)   // 4096 rows

// Scratch (device globals; no allocation allowed)
__device__ float g_proj[MM * EE];

// fp16 operand arrays
__device__ __align__(16) __half g_Ax_hi[MM * EE];       // x split (qkv gemm A)
__device__ __align__(16) __half g_Ax_lo[MM * EE];
__device__ __align__(16) __half g_Qh[16 * 2048 * 64];   // [bh][s][d]
__device__ __align__(16) __half g_Ql[16 * 2048 * 64];
__device__ __align__(16) __half g_Kh[16 * 2048 * 64];
__device__ __align__(16) __half g_Kl[16 * 2048 * 64];
__device__ __align__(16) __half g_Vh[16 * 2048 * 64];   // single fp16
__device__ __align__(16) __half g_Av[MM * EE];          // attention out, single fp16
__device__ __align__(16) __half g_Bqkv_hi[3 * EE * EE]; // [n=z*512+h*64+d][e]
__device__ __align__(16) __half g_Bqkv_lo[3 * EE * EE];
__device__ __align__(16) __half g_Bp_hi[EE * EE];       // [n][k] = Wp[n][k]
__device__ __align__(16) __half g_Bp_lo[EE * EE];

// ---------------------------------------------------------------------------
// helpers
// ---------------------------------------------------------------------------
__device__ __forceinline__ uint32_t smem_u32(const void* p) {
    uint32_t a;
    asm("{ .reg .u64 t; cvta.to.shared.u64 t, %1; cvt.u32.u64 %0, t; }"
        : "=r"(a) : "l"(p));
    return a;
}
__device__ __forceinline__ uint32_t sw128(uint32_t off) {
    return off ^ ((off >> 3) & 0x70);
}
__device__ __forceinline__ void cpasync16(uint32_t dst, const void* src) {
    asm volatile("cp.async.cg.shared.global [%0], [%1], 16;"
                 :: "r"(dst), "l"(src) : "memory");
}
template <int N>
__device__ __forceinline__ void waitg() {
    asm volatile("cp.async.wait_group %0;" :: "n"(N) : "memory");
}
__device__ __forceinline__ void commitg() {
    asm volatile("cp.async.commit_group;" ::: "memory");
}
__device__ __forceinline__ void ldsm4(uint32_t& r0, uint32_t& r1, uint32_t& r2,
                                      uint32_t& r3, uint32_t a) {
    asm volatile("ldmatrix.sync.aligned.m8n8.x4.shared.b16 {%0,%1,%2,%3}, [%4];"
                 : "=r"(r0), "=r"(r1), "=r"(r2), "=r"(r3) : "r"(a));
}
__device__ __forceinline__ void ldsm4t(uint32_t& r0, uint32_t& r1, uint32_t& r2,
                                       uint32_t& r3, uint32_t a) {
    asm volatile("ldmatrix.sync.aligned.m8n8.x4.trans.shared.b16 {%0,%1,%2,%3}, [%4];"
                 : "=r"(r0), "=r"(r1), "=r"(r2), "=r"(r3) : "r"(a));
}
__device__ __forceinline__ void mma16816(float* c, const uint32_t* a,
                                         uint32_t b0, uint32_t b1) {
    asm volatile(
        "mma.sync.aligned.m16n8k16.row.col.f32.f16.f16.f32 "
        "{%0,%1,%2,%3}, {%4,%5,%6,%7}, {%8,%9}, {%0,%1,%2,%3};"
        : "+f"(c[0]), "+f"(c[1]), "+f"(c[2]), "+f"(c[3])
        : "r"(a[0]), "r"(a[1]), "r"(a[2]), "r"(a[3]), "r"(b0), "r"(b1));
}
__device__ __forceinline__ uint32_t packh2(float a, float b) {
    __half ha = __float2half_rn(a), hb = __float2half_rn(b);
    return (uint32_t)__half_as_ushort(ha) |
           ((uint32_t)__half_as_ushort(hb) << 16);
}
__device__ __forceinline__ void split2h(float a, float b, uint32_t& hi, uint32_t& lo) {
    __half ha = __float2half_rn(a), hb = __float2half_rn(b);
    float ra = a - __half2float(ha), rb = b - __half2float(hb);
    hi = (uint32_t)__half_as_ushort(ha) |
         ((uint32_t)__half_as_ushort(hb) << 16);
    __half la = __float2half_rn(ra), lb = __float2half_rn(rb);
    lo = (uint32_t)__half_as_ushort(la) |
         ((uint32_t)__half_as_ushort(lb) << 16);
}

// ---------------------------------------------------------------------------
// Merged, vectorized prep: wqkv hi/lo, wp hi/lo, x hi/lo — ONE launch,
// 4 elements per thread.
// ---------------------------------------------------------------------------
#define N_WQKV (3 * EE * EE)            // 786432
#define N_WP   (EE * EE)                // 262144
#define N_X    (MM * EE)                // 2097152
#define PREP_BLOCKS ((N_WQKV + N_WP + N_X) / 4 / 256)   // 3072

__global__ void prep_all_kernel(const float* __restrict__ Wq,
                                const float* __restrict__ Wk,
                                const float* __restrict__ Wv,
                                const float* __restrict__ Wp,
                                const float* __restrict__ x) {
    int idx = (blockIdx.x * 256 + threadIdx.x) * 4;
    if (idx < N_WQKV) {
        int n = idx >> 9, e0 = idx & 511;
        int z = n >> 9, h = (n >> 6) & 7, d = n & 63;
        const float* W = (z == 0) ? Wq : ((z == 1) ? Wk : Wv);
        uint32_t h0, l0, h1, l1;
        float v0 = W[((size_t)h * EE + e0 + 0) * DD + d];
        float v1 = W[((size_t)h * EE + e0 + 1) * DD + d];
        float v2 = W[((size_t)h * EE + e0 + 2) * DD + d];
        float v3 = W[((size_t)h * EE + e0 + 3) * DD + d];
        split2h(v0, v1, h0, l0);
        split2h(v2, v3, h1, l1);
        *(uint2*)(g_Bqkv_hi + idx) = make_uint2(h0, h1);
        *(uint2*)(g_Bqkv_lo + idx) = make_uint2(l0, l1);
    } else if (idx < N_WQKV + N_WP) {
        int i = idx - N_WQKV;
        float4 v = *(const float4*)(Wp + i);
        uint32_t h0, l0, h1, l1;
        split2h(v.x, v.y, h0, l0);
        split2h(v.z, v.w, h1, l1);
        *(uint2*)(g_Bp_hi + i) = make_uint2(h0, h1);
        *(uint2*)(g_Bp_lo + i) = make_uint2(l0, l1);
    } else {
        int i = idx - N_WQKV - N_WP;
        float4 v = *(const float4*)(x + i);
        uint32_t h0, l0, h1, l1;
        split2h(v.x, v.y, h0, l0);
        split2h(v.z, v.w, h1, l1);
        *(uint2*)(g_Ax_hi + i) = make_uint2(h0, h1);
        *(uint2*)(g_Ax_lo + i) = make_uint2(l0, l1);
    }
}

// ---------------------------------------------------------------------------
// mma.sync GEMM: C[128 x 128] tile of A[M x 512] * B[N x 512]^T. fp32 accum.
// mode 0: qkv (N=1536). Q/K tiles (y<8): 3-pass (AhBh+AhBl+AlBh) -> hi/lo.
//         V tiles (y>=8): 2-pass (AhBh+AlBh) -> single fp16.
// mode 1: proj (N=512), A = g_Av single fp16: 2-pass (AhBh+AhBl) -> g_proj.
// 256 threads = 8 warps (4m x 2n). 3-stage cp.async pipeline (k=64).
// ---------------------------------------------------------------------------
#define STAGE_BYTES 65536
#define GEMM_SMEM (3 * STAGE_BYTES)   // 196608

__global__ __launch_bounds__(256, 1)
void gemm_mma_kernel(int mode, const float* __restrict__ x,
                     const float* __restrict__ bp) {
    extern __shared__ char sm[];
    const uint32_t smb = smem_u32(sm);
    const int t = threadIdx.x;
    const int w = t >> 5, l = t & 31;
    const int wm = w & 3, wn = w >> 2;
    const int gid = l >> 2, tig = l & 3;
    const int m0 = blockIdx.x * 128;
    const int n0 = blockIdx.y * 128;

    const bool useAl = (mode == 0);                         // pass Al·Bh
    const bool useBl = (mode == 1) || (blockIdx.y < 8);     // pass Ah·Bl

    const __half* Ah_g = (mode == 0) ? g_Ax_hi : g_Av;
    const __half* Al_g = g_Ax_lo;
    const __half* Bh_g = (mode == 0) ? g_Bqkv_hi : g_Bp_hi;
    const __half* Bl_g = (mode == 0) ? g_Bqkv_lo : g_Bp_lo;

    float acc[2][8][4];
#pragma unroll
    for (int i = 0; i < 2; i++)
#pragma unroll
        for (int j = 0; j < 8; j++)
#pragma unroll
            for (int c = 0; c < 4; c++) acc[i][j][c] = 0.f;

    auto issue_stage = [&](int s) {
        const int k0 = s * 64;
        const uint32_t sb = smb + (s % 3) * STAGE_BYTES;
        const __half* gsrc[4] = {Ah_g, Al_g, Bh_g, Bl_g};
#pragma unroll
        for (int tl = 0; tl < 4; tl++) {
            if (tl == 1 && !useAl) continue;
            if (tl == 3 && !useBl) continue;
            const uint32_t tbase = sb + tl * 16384;
            const __half* g = gsrc[tl];
            const int rbase = (tl < 2) ? m0 : n0;
#pragma unroll
            for (int i = 0; i < 4; i++) {
                int c = t + 256 * i;
                int row = c >> 3, cb = c & 7;
                uint32_t dst = tbase + sw128((uint32_t)(row * 128 + cb * 16));
                const __half* src =
                    g + (size_t)(rbase + row) * EE + k0 + cb * 8;
                cpasync16(dst, src);
            }
        }
        commitg();
    };

    issue_stage(0);
    issue_stage(1);

    const int li = l >> 3;
    const int lr = l & 7;

    for (int s = 0; s < 8; s++) {
        if (s < 7) waitg<1>(); else waitg<0>();
        __syncthreads();
        if (s + 2 < 8) issue_stage(s + 2);

        const uint32_t sb = smb + (s % 3) * STAGE_BYTES;

#pragma unroll
        for (int kk = 0; kk < 4; kk++) {
            uint32_t ah[2][4], al[2][4];
#pragma unroll
            for (int mt = 0; mt < 2; mt++) {
                int row = wm * 32 + mt * 16 + (li & 1) * 8 + lr;
                int cb = kk * 2 + (li >> 1);
                uint32_t off = sw128((uint32_t)(row * 128 + cb * 16));
                ldsm4(ah[mt][0], ah[mt][1], ah[mt][2], ah[mt][3], sb + off);
                if (useAl)
                    ldsm4(al[mt][0], al[mt][1], al[mt][2], al[mt][3],
                          sb + 16384 + off);
            }
#pragma unroll
            for (int h2 = 0; h2 < 2; h2++) {
                uint32_t bh[2][4], bl[2][4];
#pragma unroll
                for (int p2 = 0; p2 < 2; p2++) {
                    int ntb = h2 * 2 + p2;
                    int nrow = wn * 64 + ntb * 16 + (li >> 1) * 8 + lr;
                    int cb = kk * 2 + (li & 1);
                    uint32_t off = sw128((uint32_t)(nrow * 128 + cb * 16));
                    ldsm4(bh[p2][0], bh[p2][1], bh[p2][2], bh[p2][3],
                          sb + 32768 + off);
                    if (useBl)
                        ldsm4(bl[p2][0], bl[p2][1], bl[p2][2], bl[p2][3],
                              sb + 49152 + off);
                }
#pragma unroll
                for (int mt = 0; mt < 2; mt++)
#pragma unroll
                    for (int q = 0; q < 4; q++) {
                        int nt = h2 * 4 + q;
                        int p2 = q >> 1, od = q & 1;
                        float* c = acc[mt][nt];
                        mma16816(c, ah[mt], bh[p2][2 * od], bh[p2][2 * od + 1]);
                        if (useBl)
                            mma16816(c, ah[mt], bl[p2][2 * od], bl[p2][2 * od + 1]);
                        if (useAl)
                            mma16816(c, al[mt], bh[p2][2 * od], bh[p2][2 * od + 1]);
                    }
            }
        }
    }

    // ---- epilogue ----
    const int row0 = m0 + wm * 32 + gid;
    if (mode == 0) {
#pragma unroll
        for (int mt = 0; mt < 2; mt++) {
            int rg = row0 + mt * 16;
            int b = rg >> 11, sI = rg & 2047;
#pragma unroll
            for (int nt = 0; nt < 8; nt++) {
                int ng = n0 + wn * 64 + nt * 8 + 2 * tig;
                int z = ng >> 9, r9 = ng & 511;
                int h = r9 >> 6, d = r9 & 63;
                size_t base = (((size_t)(b * HH + h)) * SS + sI) * DD + d;
                if (z == 2) {
                    *(uint32_t*)(g_Vh + base) =
                        packh2(acc[mt][nt][0], acc[mt][nt][1]);
                    *(uint32_t*)(g_Vh + base + 8 * DD) =
                        packh2(acc[mt][nt][2], acc[mt][nt][3]);
                } else {
                    __half* oh = (z == 0) ? g_Qh : g_Kh;
                    __half* ol = (z == 0) ? g_Ql : g_Kl;
                    uint32_t hi, lo;
                    split2h(acc[mt][nt][0], acc[mt][nt][1], hi, lo);
                    *(uint32_t*)(oh + base) = hi;
                    *(uint32_t*)(ol + base) = lo;
                    split2h(acc[mt][nt][2], acc[mt][nt][3], hi, lo);
                    *(uint32_t*)(oh + base + 8 * DD) = hi;
                    *(uint32_t*)(ol + base + 8 * DD) = lo;
                }
            }
        }
    } else {
#pragma unroll
        for (int mt = 0; mt < 2; mt++) {
            int rg = row0 + mt * 16;
#pragma unroll
            for (int nt = 0; nt < 8; nt++) {
                int ng = n0 + wn * 64 + nt * 8 + 2 * tig;
                float2 bpv = *(const float2*)(bp + ng);
                float2 x0 = *(const float2*)(x + (size_t)rg * EE + ng);
                float2 x1 = *(const float2*)(x + (size_t)(rg + 8) * EE + ng);
                *(float2*)(g_proj + (size_t)rg * EE + ng) =
                    make_float2(acc[mt][nt][0] + bpv.x + x0.x,
                                acc[mt][nt][1] + bpv.y + x0.y);
                *(float2*)(g_proj + (size_t)(rg + 8) * EE + ng) =
                    make_float2(acc[mt][nt][2] + bpv.x + x1.x,
                                acc[mt][nt][3] + bpv.y + x1.y);
            }
        }
    }
}

// ---------------------------------------------------------------------------
// Flash attention: fp16 mma, fp32 accum. QK^T 3-pass (Q,K hi/lo);
// PV 1-pass (P fp16 x V fp16 — P rounding error scales with O, rel ~3e-4).
// q-tile 128 rows, k-tiles of 64, 8 warps, 3-stage pipeline,
// warp-level masked-strip skip.
// ---------------------------------------------------------------------------
#define NEG_BIG (-1e30f)
#define SM_QH 0
#define SM_QL 16384
#define SM_STG 32768
#define STG_SZ 24576          // Kh 8K + Kl 8K + V 8K
#define OFF_KH 0
#define OFF_KL 8192
#define OFF_V 16384
#define ATTN_SMEM (SM_STG + 3 * STG_SZ)   // 106496

__global__ __launch_bounds__(256, 1)
void attn_mma_kernel() {
    extern __shared__ char sm[];
    const uint32_t smb = smem_u32(sm);
    const int t = threadIdx.x;
    const int w = t >> 5, l = t & 31;
    const int gid = l >> 2, tig = l & 3;
    const int li = l >> 3, lr = l & 7;

    const int bid = blockIdx.x;
    const int bh = bid & 15;
    const int qt = 15 - (bid >> 4);       // heavy tiles first
    const int b = bh >> 3, h = bh & 7;
    const int qs = qt * 128;
    const size_t bhoff = (size_t)bh * SS * DD;
    const int ktmax = 2 * qt + 1;

    // ---- issue Q (128x64 hi+lo); joins commit group of stage 0 ----
#pragma unroll
    for (int arr = 0; arr < 2; arr++) {
        const __half* g = arr ? g_Ql : g_Qh;
        uint32_t base = smb + (arr ? SM_QL : SM_QH);
#pragma unroll
        for (int i = 0; i < 4; i++) {
            int c = t + 256 * i;
            int row = c >> 3, cb = c & 7;
            cpasync16(base + sw128((uint32_t)(row * 128 + cb * 16)),
                      g + bhoff + (size_t)(qs + row) * DD + cb * 8);
        }
    }

    auto issue_stage = [&](int kt) {
        const uint32_t sb = smb + SM_STG + (kt % 3) * STG_SZ;
        const __half* gs[3] = {g_Kh, g_Kl, g_Vh};
        const int ks = kt * 64;
#pragma unroll
        for (int arr = 0; arr < 3; arr++) {
#pragma unroll
            for (int i = 0; i < 2; i++) {
                int c = t + 256 * i;
                int row = c >> 3, cb = c & 7;
                cpasync16(sb + arr * 8192 + sw128((uint32_t)(row * 128 + cb * 16)),
                          gs[arr] + bhoff + (size_t)(ks + row) * DD + cb * 8);
            }
        }
        commitg();
    };

    issue_stage(0);
    issue_stage(1);

    float O[8][4];
#pragma unroll
    for (int i = 0; i < 8; i++)
#pragma unroll
        for (int j = 0; j < 4; j++) O[i][j] = 0.f;
    float m0 = NEG_BIG, m1 = NEG_BIG, l0 = 0.f, l1 = 0.f;

    const int rowstrip = qs + w * 16;
    const int qg0 = rowstrip + gid;
    const int qg1 = qg0 + 8;

    for (int kt = 0; kt <= ktmax; kt++) {
        if (kt < ktmax) waitg<1>(); else waitg<0>();
        __syncthreads();
        if (kt + 2 <= ktmax) issue_stage(kt + 2);

        const uint32_t sb = smb + SM_STG + (kt % 3) * STG_SZ;
        const int ks = kt * 64;

        // warp-uniform skip: this warp's 16-row strip fully masked
        if (ks > rowstrip + 15) continue;

        // ---- S = Q K^T (3-pass fp16 hi/lo, fp32 acc) ----
        float S[8][4];
#pragma unroll
        for (int i = 0; i < 8; i++)
#pragma unroll
            for (int j = 0; j < 4; j++) S[i][j] = 0.f;

#pragma unroll
        for (int kk = 0; kk < 4; kk++) {
            uint32_t qh[4], ql[4];
            {
                int row = w * 16 + (li & 1) * 8 + lr;
                int cb = kk * 2 + (li >> 1);
                uint32_t off = sw128((uint32_t)(row * 128 + cb * 16));
                ldsm4(qh[0], qh[1], qh[2], qh[3], smb + SM_QH + off);
                ldsm4(ql[0], ql[1], ql[2], ql[3], smb + SM_QL + off);
            }
#pragma unroll
            for (int nb = 0; nb < 4; nb++) {
                uint32_t kh[4], kl[4];
                int nrow = nb * 16 + (li >> 1) * 8 + lr;
                int cb = kk * 2 + (li & 1);
                uint32_t off = sw128((uint32_t)(nrow * 128 + cb * 16));
                ldsm4(kh[0], kh[1], kh[2], kh[3], sb + OFF_KH + off);
                ldsm4(kl[0], kl[1], kl[2], kl[3], sb + OFF_KL + off);
#pragma unroll
                for (int od = 0; od < 2; od++) {
                    float* c = S[nb * 2 + od];
                    mma16816(c, qh, kh[2 * od], kh[2 * od + 1]);
                    mma16816(c, qh, kl[2 * od], kl[2 * od + 1]);
                    mma16816(c, ql, kh[2 * od], kh[2 * od + 1]);
                }
            }
        }

        // ---- causal mask ----
        if (ks + 63 > rowstrip) {
#pragma unroll
            for (int nt = 0; nt < 8; nt++) {
                int c0 = ks + nt * 8 + 2 * tig;
                if (c0 > qg0) S[nt][0] = NEG_BIG;
                if (c0 + 1 > qg0) S[nt][1] = NEG_BIG;
                if (c0 > qg1) S[nt][2] = NEG_BIG;
                if (c0 + 1 > qg1) S[nt][3] = NEG_BIG;
            }
        }

        // ---- online softmax ----
        float mx0 = NEG_BIG, mx1 = NEG_BIG;
#pragma unroll
        for (int nt = 0; nt < 8; nt++) {
            mx0 = fmaxf(mx0, fmaxf(S[nt][0], S[nt][1]));
            mx1 = fmaxf(mx1, fmaxf(S[nt][2], S[nt][3]));
        }
        mx0 = fmaxf(mx0, __shfl_xor_sync(0xffffffffu, mx0, 1));
        mx0 = fmaxf(mx0, __shfl_xor_sync(0xffffffffu, mx0, 2));
        mx1 = fmaxf(mx1, __shfl_xor_sync(0xffffffffu, mx1, 1));
        mx1 = fmaxf(mx1, __shfl_xor_sync(0xffffffffu, mx1, 2));

        float mn0 = fmaxf(m0, mx0), mn1 = fmaxf(m1, mx1);
        float sc0 = __expf(m0 - mn0), sc1 = __expf(m1 - mn1);
        float rs0 = 0.f, rs1 = 0.f;
#pragma unroll
        for (int nt = 0; nt < 8; nt++) {
            S[nt][0] = __expf(S[nt][0] - mn0);
            S[nt][1] = __expf(S[nt][1] - mn0);
            S[nt][2] = __expf(S[nt][2] - mn1);
            S[nt][3] = __expf(S[nt][3] - mn1);
            rs0 += S[nt][0] + S[nt][1];
            rs1 += S[nt][2] + S[nt][3];
        }
        rs0 += __shfl_xor_sync(0xffffffffu, rs0, 1);
        rs0 += __shfl_xor_sync(0xffffffffu, rs0, 2);
        rs1 += __shfl_xor_sync(0xffffffffu, rs1, 1);
        rs1 += __shfl_xor_sync(0xffffffffu, rs1, 2);
        l0 = l0 * sc0 + rs0;
        l1 = l1 * sc1 + rs1;
        m0 = mn0; m1 = mn1;
#pragma unroll
        for (int dt = 0; dt < 8; dt++) {
            O[dt][0] *= sc0; O[dt][1] *= sc0;
            O[dt][2] *= sc1; O[dt][3] *= sc1;
        }

        // ---- O += P V (1-pass: P fp16 x V fp16, fp32 acc) ----
#pragma unroll
        for (int kc = 0; kc < 4; kc++) {
            uint32_t pa[4];
            pa[0] = packh2(S[2 * kc][0],     S[2 * kc][1]);
            pa[1] = packh2(S[2 * kc][2],     S[2 * kc][3]);
            pa[2] = packh2(S[2 * kc + 1][0], S[2 * kc + 1][1]);
            pa[3] = packh2(S[2 * kc + 1][2], S[2 * kc + 1][3]);
#pragma unroll
            for (int db = 0; db < 4; db++) {
                uint32_t vh[4];
                int trow = kc * 16 + (li & 1) * 8 + lr;
                int dcb = (db * 16 + (li >> 1) * 8) * 2;
                uint32_t off = sw128((uint32_t)(trow * 128 + dcb));
                ldsm4t(vh[0], vh[1], vh[2], vh[3], sb + OFF_V + off);
#pragma unroll
                for (int od = 0; od < 2; od++)
                    mma16816(O[db * 2 + od], pa, vh[2 * od], vh[2 * od + 1]);
            }
        }
    }

    // ---- epilogue: vals[b, s, (7-h)*64+d] as single fp16 ----
    const float inv0 = 1.f / l0, inv1 = 1.f / l1;
    const int colbase = (HH - 1 - h) * DD;
#pragma unroll
    for (int dt = 0; dt < 8; dt++) {
        int d = dt * 8 + 2 * tig;
        size_t i0 = ((size_t)(b * SS + qg0)) * EE + colbase + d;
        size_t i1 = ((size_t)(b * SS + qg1)) * EE + colbase + d;
        *(uint32_t*)(g_Av + i0) = packh2(O[dt][0] * inv0, O[dt][1] * inv0);
        *(uint32_t*)(g_Av + i1) = packh2(O[dt][2] * inv1, O[dt][3] * inv1);
    }
}

// ---------------------------------------------------------------------------
// LayerNorm per row of 512.
// ---------------------------------------------------------------------------
__global__ void ln_kernel(const float* __restrict__ gamma,
                          const float* __restrict__ beta,
                          float* __restrict__ out) {
    const int row = blockIdx.x;
    const float* v = g_proj + (size_t)row * EE;
    const int t = threadIdx.x;

    float a0 = v[t], a1 = v[t + 256];
    float s = a0 + a1;
    float q = a0 * a0 + a1 * a1;

#pragma unroll
    for (int off = 16; off; off >>= 1) {
        s += __shfl_xor_sync(0xffffffffu, s, off);
        q += __shfl_xor_sync(0xffffffffu, q, off);
    }
    __shared__ float ss[8], sq[8];
    int w = t >> 5, lane = t & 31;
    if (lane == 0) { ss[w] = s; sq[w] = q; }
    __syncthreads();

    float S = 0.f, Q2 = 0.f;
#pragma unroll
    for (int i = 0; i < 8; i++) { S += ss[i]; Q2 += sq[i]; }

    float mu  = S * (1.f / EE);
    float var = Q2 * (1.f / EE) - mu * mu;
    float inv = rsqrtf(var + 1e-5f);

    out[(size_t)row * EE + t]       = (a0 - mu) * inv * gamma[t]       + beta[t];
    out[(size_t)row * EE + t + 256] = (a1 - mu) * inv * gamma[t + 256] + beta[t + 256];
}

// ---------------------------------------------------------------------------
extern "C" void kernel_launch(void* const* d_in, const int* in_sizes, int n_in,
                              void* d_out, int out_size) {
    const float* x     = (const float*)d_in[0];
    const float* Wq    = (const float*)d_in[1];
    const float* Wk    = (const float*)d_in[2];
    const float* Wv    = (const float*)d_in[3];
    const float* Wp    = (const float*)d_in[4];
    const float* bp    = (const float*)d_in[5];
    const float* gamma = (const float*)d_in[6];
    const float* beta  = (const float*)d_in[7];
    float* out = (float*)d_out;

    cudaFuncSetAttribute(gemm_mma_kernel, cudaFuncAttributeMaxDynamicSharedMemorySize, GEMM_SMEM);
    cudaFuncSetAttribute(attn_mma_kernel, cudaFuncAttributeMaxDynamicSharedMemorySize, ATTN_SMEM);

    prep_all_kernel<<<PREP_BLOCKS, 256>>>(Wq, Wk, Wv, Wp, x);

    gemm_mma_kernel<<<dim3(MM / 128, 12), 256, GEMM_SMEM>>>(0, x, bp);
    attn_mma_kernel<<<256, 256, ATTN_SMEM>>>();
    gemm_mma_kernel<<<dim3(MM / 128, 4), 256, GEMM_SMEM>>>(1, x, bp);
    ln_kernel<<<MM, 256>>>(gamma, beta, out);
}